// round 12
// baseline (speedup 1.0000x reference)
#include <cuda_runtime.h>
#include <cuda_bf16.h>
#include <cstdint>

#define B 2
#define L 1536
#define D 768
#define H 12
#define DK 64
#define BLD ((size_t)B * L * D)
#define DD  ((size_t)D * D)

// ---------------------------------------------------------------------------
// Scratch (allocation-free rule: static __device__ arrays)
// ---------------------------------------------------------------------------
__device__ __nv_bfloat16 g_xqh[BLD], g_xql[BLD];
__device__ __nv_bfloat16 g_xkh[BLD], g_xkl[BLD];
__device__ __nv_bfloat16 g_wqh[DD],  g_wql[DD];
__device__ __nv_bfloat16 g_wkh[DD],  g_wkl[DD];
__device__ __nv_bfloat16 g_qh[BLD], g_ql[BLD];
__device__ __nv_bfloat16 g_kh[BLD], g_kl[BLD];
__device__ __nv_bfloat16 g_khd[BLD], g_kld[BLD];   // dense (valid-only) K rows
__device__ float g_s[(size_t)B * H * L * L];       // z, dense-compacted columns

__device__ int            g_nv[B];
__device__ unsigned short g_cols[B][L];            // dense -> col

__device__ __forceinline__ uint32_t smem_u32(const void* p) {
    uint32_t a;
    asm("{ .reg .u64 t; cvta.to.shared.u64 t, %1; cvt.u32.u64 %0, t; }" : "=r"(a) : "l"(p));
    return a;
}
__device__ __forceinline__ void ldsm_x4(uint32_t addr, uint32_t& r0, uint32_t& r1,
                                        uint32_t& r2, uint32_t& r3) {
    asm volatile("ldmatrix.sync.aligned.m8n8.x4.shared.b16 {%0,%1,%2,%3}, [%4];"
                 : "=r"(r0), "=r"(r1), "=r"(r2), "=r"(r3) : "r"(addr));
}
__device__ __forceinline__ void ldsm_x2(uint32_t addr, uint32_t& r0, uint32_t& r1) {
    asm volatile("ldmatrix.sync.aligned.m8n8.x2.shared.b16 {%0,%1}, [%2];"
                 : "=r"(r0), "=r"(r1) : "r"(addr));
}
__device__ __forceinline__ void mma_bf16(float* c, const uint32_t* a, const uint32_t* b) {
    asm volatile(
        "mma.sync.aligned.m16n8k16.row.col.f32.bf16.bf16.f32 "
        "{%0,%1,%2,%3}, {%4,%5,%6,%7}, {%8,%9}, {%0,%1,%2,%3};"
        : "+f"(c[0]), "+f"(c[1]), "+f"(c[2]), "+f"(c[3])
        : "r"(a[0]), "r"(a[1]), "r"(a[2]), "r"(a[3]), "r"(b[0]), "r"(b[1]));
}
__device__ __forceinline__ void cpa16(uint32_t s, const void* g) {
    asm volatile("cp.async.cg.shared.global [%0], [%1], 16;" :: "r"(s), "l"(g));
}
#define CPA_COMMIT() asm volatile("cp.async.commit_group;" ::: "memory")
#define CPA_WAIT1()  asm volatile("cp.async.wait_group 1;" ::: "memory")
#define CPA_WAIT0()  asm volatile("cp.async.wait_group 0;" ::: "memory")

// ---------------------------------------------------------------------------
// Phase -1: build column compaction (per batch): nv, cols.
// ---------------------------------------------------------------------------
__global__ void build_colmap_kernel(const int* __restrict__ mask)
{
    int b = blockIdx.x;
    int t = threadIdx.x;
    __shared__ int s[512];

    int m0 = mask[b * L + 3 * t + 0] != 0;
    int m1 = mask[b * L + 3 * t + 1] != 0;
    int m2 = mask[b * L + 3 * t + 2] != 0;
    int cnt = m0 + m1 + m2;
    s[t] = cnt;
    __syncthreads();
    for (int off = 1; off < 512; off <<= 1) {
        int v = (t >= off) ? s[t - off] : 0;
        __syncthreads();
        s[t] += v;
        __syncthreads();
    }
    int d = s[t] - cnt;
    if (t == 511) g_nv[b] = s[511];

    int col = 3 * t;
    if (m0) g_cols[b][d++] = (unsigned short)col;
    col++;
    if (m1) g_cols[b][d++] = (unsigned short)col;
    col++;
    if (m2) g_cols[b][d] = (unsigned short)col;
}

// ---------------------------------------------------------------------------
// Phase 0: fp32 -> bf16 hi/lo split of ALL four sources, ONE launch.
// ---------------------------------------------------------------------------
__global__ void split_all_kernel(const float* __restrict__ query,
                                 const float* __restrict__ key,
                                 const float* __restrict__ wq,
                                 const float* __restrict__ wk)
{
    const int n4x = (int)(BLD / 4);
    const int n4w = (int)(DD / 4);
    int i = blockIdx.x * blockDim.x + threadIdx.x;

    const float* src;
    __nv_bfloat16 *dh, *dl;
    int li;
    if (i < 2 * n4x) {
        if (i < n4x) { src = query; dh = g_xqh; dl = g_xql; li = i; }
        else         { src = key;   dh = g_xkh; dl = g_xkl; li = i - n4x; }
    } else {
        int j = i - 2 * n4x;
        if (j >= 2 * n4w) return;
        if (j < n4w) { src = wq; dh = g_wqh; dl = g_wql; li = j; }
        else         { src = wk; dh = g_wkh; dl = g_wkl; li = j - n4w; }
    }

    float4 v = ((const float4*)src)[li];
    __nv_bfloat16 h[4], l[4];
    const float* f = &v.x;
    #pragma unroll
    for (int j = 0; j < 4; j++) {
        h[j] = __float2bfloat16(f[j]);
        l[j] = __float2bfloat16(f[j] - __bfloat162float(h[j]));
    }
    ((uint2*)dh)[li] = *(uint2*)h;
    ((uint2*)dl)[li] = *(uint2*)l;
}

// ---------------------------------------------------------------------------
// Phase 1: projection via HMMA bf16x3, cp.async double-buffered K loop.
// ---------------------------------------------------------------------------
#define RP 72
#define P_AH 0
#define P_AL (128 * RP)
#define P_BH (2 * 128 * RP)
#define P_BL (2 * 128 * RP + 256 * RP)
#define PROJ_BUF (2 * 128 * RP + 2 * 256 * RP)
#define PROJ_SM_BYTES (2 * PROJ_BUF * 2)

__global__ void __launch_bounds__(512, 1) proj_mma_kernel(
    const float* __restrict__ biasq, const float* __restrict__ biask)
{
    extern __shared__ __nv_bfloat16 sm[];
    const uint32_t sm_b = smem_u32(sm);

    int nt = blockIdx.x, mt = blockIdx.y, which = blockIdx.z;
    int tid = threadIdx.x;
    int wid = tid >> 5, lane = tid & 31;

    const __nv_bfloat16* xh = which ? g_xkh : g_xqh;
    const __nv_bfloat16* xl = which ? g_xkl : g_xql;
    const __nv_bfloat16* wh = which ? g_wkh : g_wqh;
    const __nv_bfloat16* wl = which ? g_wkl : g_wql;
    __nv_bfloat16* oh = which ? g_kh : g_qh;
    __nv_bfloat16* ol = which ? g_kl : g_ql;
    const float* bias = which ? biask : biasq;

    int wm = (wid & 1) * 64;
    int wn = (wid >> 1) * 32;

    float acc[4][4][4];
    #pragma unroll
    for (int i = 0; i < 4; i++)
        #pragma unroll
        for (int j = 0; j < 4; j++)
            #pragma unroll
            for (int r = 0; r < 4; r++) acc[i][j][r] = 0.f;

    int a_row = lane & 15;
    int a_kh8 = (lane >> 4) * 8;
    int b_row = lane & 7;
    int b_kh8 = ((lane >> 3) & 1) * 8;

    int lrowA[2], lc8A[2], lrowB[4], lc8B[4];
    #pragma unroll
    for (int it = 0; it < 2; it++) { int idx = tid + it * 512; lrowA[it] = idx >> 3; lc8A[it] = (idx & 7) * 8; }
    #pragma unroll
    for (int it = 0; it < 4; it++) { int idx = tid + it * 512; lrowB[it] = idx >> 3; lc8B[it] = (idx & 7) * 8; }

    auto prefetch = [&](int kc, int pb) {
        uint32_t base = sm_b + (uint32_t)pb * PROJ_BUF * 2;
        #pragma unroll
        for (int it = 0; it < 2; it++) {
            size_t g = (size_t)(mt * 128 + lrowA[it]) * D + kc + lc8A[it];
            uint32_t so = (uint32_t)(lrowA[it] * RP + lc8A[it]) * 2;
            cpa16(base + P_AH * 2 + so, xh + g);
            cpa16(base + P_AL * 2 + so, xl + g);
        }
        #pragma unroll
        for (int it = 0; it < 4; it++) {
            size_t g = (size_t)(nt * 256 + lrowB[it]) * D + kc + lc8B[it];
            uint32_t so = (uint32_t)(lrowB[it] * RP + lc8B[it]) * 2;
            cpa16(base + P_BH * 2 + so, wh + g);
            cpa16(base + P_BL * 2 + so, wl + g);
        }
        CPA_COMMIT();
    };

    prefetch(0, 0);

    int buf = 0;
    for (int kci = 0; kci < 12; kci++) {
        if (kci < 11) { prefetch((kci + 1) * 64, buf ^ 1); CPA_WAIT1(); }
        else          { CPA_WAIT0(); }
        __syncthreads();

        uint32_t base = sm_b + (uint32_t)buf * PROJ_BUF * 2;
        uint32_t sAh_b = base + P_AH * 2, sAl_b = base + P_AL * 2;
        uint32_t sBh_b = base + P_BH * 2, sBl_b = base + P_BL * 2;

        #pragma unroll
        for (int ks = 0; ks < 4; ks++) {
            int kb = ks * 16;
            uint32_t ah[4][4], al[4][4];
            #pragma unroll
            for (int i = 0; i < 4; i++) {
                uint32_t off = (uint32_t)((wm + i * 16 + a_row) * RP + kb + a_kh8) * 2;
                ldsm_x4(sAh_b + off, ah[i][0], ah[i][1], ah[i][2], ah[i][3]);
                ldsm_x4(sAl_b + off, al[i][0], al[i][1], al[i][2], al[i][3]);
            }
            #pragma unroll
            for (int j = 0; j < 4; j++) {
                uint32_t off = (uint32_t)((wn + j * 8 + b_row) * RP + kb + b_kh8) * 2;
                uint32_t bh[2], bl[2];
                ldsm_x2(sBh_b + off, bh[0], bh[1]);
                ldsm_x2(sBl_b + off, bl[0], bl[1]);
                #pragma unroll
                for (int i = 0; i < 4; i++) {
                    mma_bf16(acc[i][j], ah[i], bh);
                    mma_bf16(acc[i][j], ah[i], bl);
                    mma_bf16(acc[i][j], al[i], bh);
                }
            }
        }
        __syncthreads();
        buf ^= 1;
    }

    int r0 = lane >> 2;
    int cp = (lane & 3) * 2;
    #pragma unroll
    for (int i = 0; i < 4; i++) {
        int grow0 = mt * 128 + wm + i * 16 + r0;
        #pragma unroll
        for (int j = 0; j < 4; j++) {
            int gcol = nt * 256 + wn + j * 8 + cp;
            float2 bv = *(const float2*)(bias + gcol);
            #pragma unroll
            for (int half = 0; half < 2; half++) {
                float v0 = acc[i][j][half * 2 + 0] + bv.x;
                float v1 = acc[i][j][half * 2 + 1] + bv.y;
                __nv_bfloat16 h0 = __float2bfloat16(v0);
                __nv_bfloat16 h1 = __float2bfloat16(v1);
                __nv_bfloat16 l0 = __float2bfloat16(v0 - __bfloat162float(h0));
                __nv_bfloat16 l1 = __float2bfloat16(v1 - __bfloat162float(h1));
                size_t addr = (size_t)(grow0 + half * 8) * D + gcol;
                __nv_bfloat16 hp[2] = {h0, h1}, lp[2] = {l0, l1};
                *(uint32_t*)(oh + addr) = *(uint32_t*)hp;
                *(uint32_t*)(ol + addr) = *(uint32_t*)lp;
            }
        }
    }
}

// ---------------------------------------------------------------------------
// Phase 1.5: gather valid K rows into dense arrays g_khd/g_kld.
// grid (L/4, B), 256 thr; each block copies 4 dense rows (hi+lo).
// ---------------------------------------------------------------------------
__global__ void gather_k_kernel()
{
    int b = blockIdx.y;
    int nv = g_nv[b];
    int d0 = blockIdx.x * 4;
    if (d0 >= nv) return;

    int t = threadIdx.x;
    // work item: 4 rows x 96 uint4 x 2 arrays = 768 items; 256 thr x 3
    #pragma unroll
    for (int i = 0; i < 3; i++) {
        int w = t + i * 256;
        int arr = w / 384;            // 0 = hi, 1 = lo
        int rem = w - arr * 384;
        int r   = rem / 96;           // row within block
        int c4  = rem - r * 96;       // uint4 col (96 per row)
        int dd  = d0 + r;
        if (dd < nv) {
            int col = g_cols[b][dd];
            const uint4* src = (const uint4*)((arr ? g_kl : g_kh) + (size_t)(b * L + col) * D);
            uint4* dst = (uint4*)((arr ? g_kld : g_khd) + (size_t)(b * L + dd) * D);
            dst[c4] = src[c4];
        }
    }
}

// ---------------------------------------------------------------------------
// Phase 2: scores via HMMA bf16x3 on DENSE K. Coalesced epilogue.
// k-tiles past nv exit immediately (live tiles ~= nv/256 per batch).
// ---------------------------------------------------------------------------
#define SC_SM_Q (128 * RP)
#define SC_SM_K (256 * RP)
#define SC_SM_BYTES ((2 * SC_SM_Q + 2 * SC_SM_K) * 2)

__global__ void __launch_bounds__(512, 1) scores_mma_kernel()
{
    extern __shared__ __nv_bfloat16 sm[];
    __nv_bfloat16* sQh = sm;
    __nv_bfloat16* sQl = sm + SC_SM_Q;
    __nv_bfloat16* sKh = sm + 2 * SC_SM_Q;
    __nv_bfloat16* sKl = sm + 2 * SC_SM_Q + SC_SM_K;

    int kt = blockIdx.x, qt = blockIdx.y, bh = blockIdx.z;
    int b = bh / H, h = bh % H;

    if (kt * 256 >= g_nv[b]) return;      // dead tile: all columns masked

    int tid = threadIdx.x;
    int wid = tid >> 5, lane = tid & 31;

    {
        const __nv_bfloat16* qhb = g_qh  + (size_t)(b * L + qt * 128) * D + h * DK;
        const __nv_bfloat16* qlb = g_ql  + (size_t)(b * L + qt * 128) * D + h * DK;
        const __nv_bfloat16* khb = g_khd + (size_t)(b * L + kt * 256) * D + h * DK;
        const __nv_bfloat16* klb = g_kld + (size_t)(b * L + kt * 256) * D + h * DK;

        #pragma unroll
        for (int it = 0; it < 2; it++) {
            int idx = tid + it * 512;
            int row = idx >> 3;
            int c8  = (idx & 7) * 8;
            *(uint4*)(sQh + row * RP + c8) = *(const uint4*)(qhb + (size_t)row * D + c8);
            *(uint4*)(sQl + row * RP + c8) = *(const uint4*)(qlb + (size_t)row * D + c8);
        }
        #pragma unroll
        for (int it = 0; it < 4; it++) {
            int idx = tid + it * 512;
            int row = idx >> 3;
            int c8  = (idx & 7) * 8;
            *(uint4*)(sKh + row * RP + c8) = *(const uint4*)(khb + (size_t)row * D + c8);
            *(uint4*)(sKl + row * RP + c8) = *(const uint4*)(klb + (size_t)row * D + c8);
        }
    }
    __syncthreads();

    int wm = (wid & 1) * 64;
    int wn = (wid >> 1) * 32;

    float acc[4][4][4];
    #pragma unroll
    for (int i = 0; i < 4; i++)
        #pragma unroll
        for (int j = 0; j < 4; j++)
            #pragma unroll
            for (int r = 0; r < 4; r++) acc[i][j][r] = 0.f;

    uint32_t sQh_b = smem_u32(sQh), sQl_b = smem_u32(sQl);
    uint32_t sKh_b = smem_u32(sKh), sKl_b = smem_u32(sKl);

    int a_row = lane & 15;
    int a_kh8 = (lane >> 4) * 8;
    int b_row = lane & 7;
    int b_kh8 = ((lane >> 3) & 1) * 8;

    #pragma unroll
    for (int ks = 0; ks < 4; ks++) {
        int kb = ks * 16;
        uint32_t ah[4][4], al[4][4];
        #pragma unroll
        for (int i = 0; i < 4; i++) {
            uint32_t off = (uint32_t)((wm + i * 16 + a_row) * RP + kb + a_kh8) * 2;
            ldsm_x4(sQh_b + off, ah[i][0], ah[i][1], ah[i][2], ah[i][3]);
            ldsm_x4(sQl_b + off, al[i][0], al[i][1], al[i][2], al[i][3]);
        }
        #pragma unroll
        for (int j = 0; j < 4; j++) {
            uint32_t off = (uint32_t)((wn + j * 8 + b_row) * RP + kb + b_kh8) * 2;
            uint32_t bh2[2], bl2[2];
            ldsm_x2(sKh_b + off, bh2[0], bh2[1]);
            ldsm_x2(sKl_b + off, bl2[0], bl2[1]);
            #pragma unroll
            for (int i = 0; i < 4; i++) {
                mma_bf16(acc[i][j], ah[i], bh2);
                mma_bf16(acc[i][j], ah[i], bl2);
                mma_bf16(acc[i][j], al[i], bh2);
            }
        }
    }

    const float scale = 1.0f / 16.0f;
    int r0 = lane >> 2;
    int cp = (lane & 3) * 2;
    #pragma unroll
    for (int i = 0; i < 4; i++) {
        int grow0 = qt * 128 + wm + i * 16 + r0;
        #pragma unroll
        for (int j = 0; j < 4; j++) {
            int gcol = kt * 256 + wn + j * 8 + cp;
            float2 v0 = make_float2(acc[i][j][0] * scale, acc[i][j][1] * scale);
            float2 v1 = make_float2(acc[i][j][2] * scale, acc[i][j][3] * scale);
            *(float2*)(g_s + ((size_t)bh * L + grow0) * L + gcol) = v0;
            *(float2*)(g_s + ((size_t)bh * L + grow0 + 8) * L + gcol) = v1;
        }
    }
}

// ---------------------------------------------------------------------------
// Phase 3: entmax-1.5 on dense-compacted rows, warp per (b,q) row.
// C=8 fast path (nv<=1024), C=12 guarded exact fallback.
// ---------------------------------------------------------------------------
template<int C>
__global__ void __launch_bounds__(128) entmax_dense_kernel(float* __restrict__ out)
{
    int warp = (blockIdx.x * blockDim.x + threadIdx.x) >> 5;
    int lane = threadIdx.x & 31;
    int b = warp / L, qi = warp % L;

    int nv = g_nv[b];
    if (C == 8) { if (nv > 1024) return; }
    else        { if (nv <= 1024) return; }

    float acc[4 * C];
    #pragma unroll
    for (int e = 0; e < 4 * C; e++) acc[e] = 0.f;

    const float invH = 1.0f / 12.0f;

    for (int h = 0; h < H; h++) {
        const float4* row = (const float4*)(g_s + ((size_t)(b * H + h) * L + qi) * L);
        float z[4 * C];
        float m = -1e30f;
        #pragma unroll
        for (int i = 0; i < C; i++) {
            int e4 = lane + i * 32;
            float4 v = __ldg(row + e4);
            z[i * 4 + 0] = (4 * e4 + 0 < nv) ? v.x : -1e30f;
            z[i * 4 + 1] = (4 * e4 + 1 < nv) ? v.y : -1e30f;
            z[i * 4 + 2] = (4 * e4 + 2 < nv) ? v.z : -1e30f;
            z[i * 4 + 3] = (4 * e4 + 3 < nv) ? v.w : -1e30f;
            m = fmaxf(m, fmaxf(fmaxf(z[i*4], z[i*4+1]), fmaxf(z[i*4+2], z[i*4+3])));
        }
        #pragma unroll
        for (int o = 16; o; o >>= 1) m = fmaxf(m, __shfl_xor_sync(0xffffffffu, m, o));

        float tau = m - 1.0f;
        const float tmax = m - 1e-7f;

        for (int it = 0; it < 20; it++) {
            float s0 = 0.f, s1 = 0.f;
            #pragma unroll
            for (int e = 0; e < 4 * C; e++) {
                float d = fmaxf(z[e] - tau, 0.f);
                s1 += d;
                s0 = fmaf(d, d, s0);
            }
            #pragma unroll
            for (int o = 16; o; o >>= 1) {
                s0 += __shfl_xor_sync(0xffffffffu, s0, o);
                s1 += __shfl_xor_sync(0xffffffffu, s1, o);
            }
            float step;
            if (s0 > 2.0f) step = (s0 - sqrtf(s0)) / s1;
            else           step = (s0 - 1.0f) / (2.0f * s1);
            tau = fminf(tau + step, tmax);
            if (fabsf(step) <= 5e-7f) break;
        }

        #pragma unroll
        for (int e = 0; e < 4 * C; e++) {
            float d = z[e] - tau;
            if (d > 0.f) acc[e] = fmaf(d * d, invH, acc[e]);
        }
    }

    float* orow = out + ((size_t)b * L + qi) * L;
    #pragma unroll
    for (int i = 0; i < 12; i++)
        ((float4*)orow)[lane + i * 32] = make_float4(0.f, 0.f, 0.f, 0.f);
    __syncwarp();
    #pragma unroll
    for (int i = 0; i < C; i++) {
        int e4 = lane + i * 32;
        if (4 * e4 < nv) {
            ushort4 c4 = *(const ushort4*)&g_cols[b][4 * e4];
            orow[c4.x] = acc[i * 4 + 0];
            if (4 * e4 + 1 < nv) orow[c4.y] = acc[i * 4 + 1];
            if (4 * e4 + 2 < nv) orow[c4.z] = acc[i * 4 + 2];
            if (4 * e4 + 3 < nv) orow[c4.w] = acc[i * 4 + 3];
        }
    }
}

// ---------------------------------------------------------------------------
extern "C" void kernel_launch(void* const* d_in, const int* in_sizes, int n_in,
                              void* d_out, int out_size)
{
    const float* query = (const float*)d_in[0];
    const float* key   = (const float*)d_in[1];
    const int*   mask  = (const int*)d_in[2];
    const float* wq_w  = (const float*)d_in[3];
    const float* wq_b  = (const float*)d_in[4];
    const float* wk_w  = (const float*)d_in[5];
    const float* wk_b  = (const float*)d_in[6];
    float* out = (float*)d_out;

    (void)in_sizes; (void)n_in; (void)out_size;

    cudaFuncSetAttribute(proj_mma_kernel,
                         cudaFuncAttributeMaxDynamicSharedMemorySize, PROJ_SM_BYTES);
    cudaFuncSetAttribute(scores_mma_kernel,
                         cudaFuncAttributeMaxDynamicSharedMemorySize, SC_SM_BYTES);

    build_colmap_kernel<<<B, 512>>>(mask);

    {
        int total4 = (int)(2 * (BLD / 4) + 2 * (DD / 4));
        split_all_kernel<<<(total4 + 255) / 256, 256>>>(query, key, wq_w, wk_w);
    }

    dim3 pgrid(D / 256, (B * L) / 128, 2);       // (3, 24, 2)
    proj_mma_kernel<<<pgrid, 512, PROJ_SM_BYTES>>>(wq_b, wk_b);

    dim3 ggrid(L / 4, B);
    gather_k_kernel<<<ggrid, 256>>>();

    dim3 sgrid(L / 256, L / 128, B * H);         // (6, 12, 24)
    scores_mma_kernel<<<sgrid, 512, SC_SM_BYTES>>>();

    entmax_dense_kernel<8><<<(B * L) / 4, 128>>>(out);
    entmax_dense_kernel<12><<<(B * L) / 4, 128>>>(out);   // guarded fallback
}

// round 13
// speedup vs baseline: 1.0075x; 1.0075x over previous
#include <cuda_runtime.h>
#include <cuda_bf16.h>
#include <cstdint>

#define B 2
#define L 1536
#define D 768
#define H 12
#define DK 64
#define BLD ((size_t)B * L * D)
#define DD  ((size_t)D * D)

// ---------------------------------------------------------------------------
// Scratch (allocation-free rule: static __device__ arrays)
// ---------------------------------------------------------------------------
__device__ __nv_bfloat16 g_xqh[BLD], g_xql[BLD];
__device__ __nv_bfloat16 g_xkh[BLD], g_xkl[BLD];
__device__ __nv_bfloat16 g_wqh[DD],  g_wql[DD];
__device__ __nv_bfloat16 g_wkh[DD],  g_wkl[DD];
__device__ __nv_bfloat16 g_qh[BLD], g_ql[BLD];
__device__ __nv_bfloat16 g_kh[BLD], g_kl[BLD];
__device__ float g_s[(size_t)B * H * L * L];       // z, dense-compacted columns

__device__ int            g_nv[B];
__device__ unsigned short g_cols[B][L];            // dense -> col (zero-init tail)

__device__ __forceinline__ uint32_t smem_u32(const void* p) {
    uint32_t a;
    asm("{ .reg .u64 t; cvta.to.shared.u64 t, %1; cvt.u32.u64 %0, t; }" : "=r"(a) : "l"(p));
    return a;
}
__device__ __forceinline__ void ldsm_x4(uint32_t addr, uint32_t& r0, uint32_t& r1,
                                        uint32_t& r2, uint32_t& r3) {
    asm volatile("ldmatrix.sync.aligned.m8n8.x4.shared.b16 {%0,%1,%2,%3}, [%4];"
                 : "=r"(r0), "=r"(r1), "=r"(r2), "=r"(r3) : "r"(addr));
}
__device__ __forceinline__ void ldsm_x2(uint32_t addr, uint32_t& r0, uint32_t& r1) {
    asm volatile("ldmatrix.sync.aligned.m8n8.x2.shared.b16 {%0,%1}, [%2];"
                 : "=r"(r0), "=r"(r1) : "r"(addr));
}
__device__ __forceinline__ void mma_bf16(float* c, const uint32_t* a, const uint32_t* b) {
    asm volatile(
        "mma.sync.aligned.m16n8k16.row.col.f32.bf16.bf16.f32 "
        "{%0,%1,%2,%3}, {%4,%5,%6,%7}, {%8,%9}, {%0,%1,%2,%3};"
        : "+f"(c[0]), "+f"(c[1]), "+f"(c[2]), "+f"(c[3])
        : "r"(a[0]), "r"(a[1]), "r"(a[2]), "r"(a[3]), "r"(b[0]), "r"(b[1]));
}
__device__ __forceinline__ void cpa16(uint32_t s, const void* g) {
    asm volatile("cp.async.cg.shared.global [%0], [%1], 16;" :: "r"(s), "l"(g));
}
#define CPA_COMMIT() asm volatile("cp.async.commit_group;" ::: "memory")
#define CPA_WAIT1()  asm volatile("cp.async.wait_group 1;" ::: "memory")
#define CPA_WAIT0()  asm volatile("cp.async.wait_group 0;" ::: "memory")

// ---------------------------------------------------------------------------
// Phase 0: fp32 -> bf16 hi/lo split of ALL four sources, ONE launch.
// ---------------------------------------------------------------------------
__global__ void split_all_kernel(const float* __restrict__ query,
                                 const float* __restrict__ key,
                                 const float* __restrict__ wq,
                                 const float* __restrict__ wk)
{
    const int n4x = (int)(BLD / 4);
    const int n4w = (int)(DD / 4);
    int i = blockIdx.x * blockDim.x + threadIdx.x;

    const float* src;
    __nv_bfloat16 *dh, *dl;
    int li;
    if (i < 2 * n4x) {
        if (i < n4x) { src = query; dh = g_xqh; dl = g_xql; li = i; }
        else         { src = key;   dh = g_xkh; dl = g_xkl; li = i - n4x; }
    } else {
        int j = i - 2 * n4x;
        if (j >= 2 * n4w) return;
        if (j < n4w) { src = wq; dh = g_wqh; dl = g_wql; li = j; }
        else         { src = wk; dh = g_wkh; dl = g_wkl; li = j - n4w; }
    }

    float4 v = ((const float4*)src)[li];
    __nv_bfloat16 h[4], l[4];
    const float* f = &v.x;
    #pragma unroll
    for (int j = 0; j < 4; j++) {
        h[j] = __float2bfloat16(f[j]);
        l[j] = __float2bfloat16(f[j] - __bfloat162float(h[j]));
    }
    ((uint2*)dh)[li] = *(uint2*)h;
    ((uint2*)dl)[li] = *(uint2*)l;
}

// ---------------------------------------------------------------------------
// Phase 0.5: build column compaction (per batch): nv, cols.
// ---------------------------------------------------------------------------
__global__ void build_colmap_kernel(const int* __restrict__ mask)
{
    int b = blockIdx.x;
    int t = threadIdx.x;
    __shared__ int s[512];

    int m0 = mask[b * L + 3 * t + 0] != 0;
    int m1 = mask[b * L + 3 * t + 1] != 0;
    int m2 = mask[b * L + 3 * t + 2] != 0;
    int cnt = m0 + m1 + m2;
    s[t] = cnt;
    __syncthreads();
    for (int off = 1; off < 512; off <<= 1) {
        int v = (t >= off) ? s[t - off] : 0;
        __syncthreads();
        s[t] += v;
        __syncthreads();
    }
    int d = s[t] - cnt;
    if (t == 511) g_nv[b] = s[511];

    int col = 3 * t;
    if (m0) g_cols[b][d++] = (unsigned short)col;
    col++;
    if (m1) g_cols[b][d++] = (unsigned short)col;
    col++;
    if (m2) g_cols[b][d] = (unsigned short)col;
}

// ---------------------------------------------------------------------------
// Phase 1: projection via HMMA bf16x3, cp.async double-buffered K loop.
// ---------------------------------------------------------------------------
#define RP 72
#define P_AH 0
#define P_AL (128 * RP)
#define P_BH (2 * 128 * RP)
#define P_BL (2 * 128 * RP + 256 * RP)
#define PROJ_BUF (2 * 128 * RP + 2 * 256 * RP)
#define PROJ_SM_BYTES (2 * PROJ_BUF * 2)

__global__ void __launch_bounds__(512, 1) proj_mma_kernel(
    const float* __restrict__ biasq, const float* __restrict__ biask)
{
    extern __shared__ __nv_bfloat16 sm[];
    const uint32_t sm_b = smem_u32(sm);

    int nt = blockIdx.x, mt = blockIdx.y, which = blockIdx.z;
    int tid = threadIdx.x;
    int wid = tid >> 5, lane = tid & 31;

    const __nv_bfloat16* xh = which ? g_xkh : g_xqh;
    const __nv_bfloat16* xl = which ? g_xkl : g_xql;
    const __nv_bfloat16* wh = which ? g_wkh : g_wqh;
    const __nv_bfloat16* wl = which ? g_wkl : g_wql;
    __nv_bfloat16* oh = which ? g_kh : g_qh;
    __nv_bfloat16* ol = which ? g_kl : g_ql;
    const float* bias = which ? biask : biasq;

    int wm = (wid & 1) * 64;
    int wn = (wid >> 1) * 32;

    float acc[4][4][4];
    #pragma unroll
    for (int i = 0; i < 4; i++)
        #pragma unroll
        for (int j = 0; j < 4; j++)
            #pragma unroll
            for (int r = 0; r < 4; r++) acc[i][j][r] = 0.f;

    int a_row = lane & 15;
    int a_kh8 = (lane >> 4) * 8;
    int b_row = lane & 7;
    int b_kh8 = ((lane >> 3) & 1) * 8;

    int lrowA[2], lc8A[2], lrowB[4], lc8B[4];
    #pragma unroll
    for (int it = 0; it < 2; it++) { int idx = tid + it * 512; lrowA[it] = idx >> 3; lc8A[it] = (idx & 7) * 8; }
    #pragma unroll
    for (int it = 0; it < 4; it++) { int idx = tid + it * 512; lrowB[it] = idx >> 3; lc8B[it] = (idx & 7) * 8; }

    auto prefetch = [&](int kc, int pb) {
        uint32_t base = sm_b + (uint32_t)pb * PROJ_BUF * 2;
        #pragma unroll
        for (int it = 0; it < 2; it++) {
            size_t g = (size_t)(mt * 128 + lrowA[it]) * D + kc + lc8A[it];
            uint32_t so = (uint32_t)(lrowA[it] * RP + lc8A[it]) * 2;
            cpa16(base + P_AH * 2 + so, xh + g);
            cpa16(base + P_AL * 2 + so, xl + g);
        }
        #pragma unroll
        for (int it = 0; it < 4; it++) {
            size_t g = (size_t)(nt * 256 + lrowB[it]) * D + kc + lc8B[it];
            uint32_t so = (uint32_t)(lrowB[it] * RP + lc8B[it]) * 2;
            cpa16(base + P_BH * 2 + so, wh + g);
            cpa16(base + P_BL * 2 + so, wl + g);
        }
        CPA_COMMIT();
    };

    prefetch(0, 0);

    int buf = 0;
    for (int kci = 0; kci < 12; kci++) {
        if (kci < 11) { prefetch((kci + 1) * 64, buf ^ 1); CPA_WAIT1(); }
        else          { CPA_WAIT0(); }
        __syncthreads();

        uint32_t base = sm_b + (uint32_t)buf * PROJ_BUF * 2;
        uint32_t sAh_b = base + P_AH * 2, sAl_b = base + P_AL * 2;
        uint32_t sBh_b = base + P_BH * 2, sBl_b = base + P_BL * 2;

        #pragma unroll
        for (int ks = 0; ks < 4; ks++) {
            int kb = ks * 16;
            uint32_t ah[4][4], al[4][4];
            #pragma unroll
            for (int i = 0; i < 4; i++) {
                uint32_t off = (uint32_t)((wm + i * 16 + a_row) * RP + kb + a_kh8) * 2;
                ldsm_x4(sAh_b + off, ah[i][0], ah[i][1], ah[i][2], ah[i][3]);
                ldsm_x4(sAl_b + off, al[i][0], al[i][1], al[i][2], al[i][3]);
            }
            #pragma unroll
            for (int j = 0; j < 4; j++) {
                uint32_t off = (uint32_t)((wn + j * 8 + b_row) * RP + kb + b_kh8) * 2;
                uint32_t bh[2], bl[2];
                ldsm_x2(sBh_b + off, bh[0], bh[1]);
                ldsm_x2(sBl_b + off, bl[0], bl[1]);
                #pragma unroll
                for (int i = 0; i < 4; i++) {
                    mma_bf16(acc[i][j], ah[i], bh);
                    mma_bf16(acc[i][j], ah[i], bl);
                    mma_bf16(acc[i][j], al[i], bh);
                }
            }
        }
        __syncthreads();
        buf ^= 1;
    }

    int r0 = lane >> 2;
    int cp = (lane & 3) * 2;
    #pragma unroll
    for (int i = 0; i < 4; i++) {
        int grow0 = mt * 128 + wm + i * 16 + r0;
        #pragma unroll
        for (int j = 0; j < 4; j++) {
            int gcol = nt * 256 + wn + j * 8 + cp;
            float2 bv = *(const float2*)(bias + gcol);
            #pragma unroll
            for (int half = 0; half < 2; half++) {
                float v0 = acc[i][j][half * 2 + 0] + bv.x;
                float v1 = acc[i][j][half * 2 + 1] + bv.y;
                __nv_bfloat16 h0 = __float2bfloat16(v0);
                __nv_bfloat16 h1 = __float2bfloat16(v1);
                __nv_bfloat16 l0 = __float2bfloat16(v0 - __bfloat162float(h0));
                __nv_bfloat16 l1 = __float2bfloat16(v1 - __bfloat162float(h1));
                size_t addr = (size_t)(grow0 + half * 8) * D + gcol;
                __nv_bfloat16 hp[2] = {h0, h1}, lp[2] = {l0, l1};
                *(uint32_t*)(oh + addr) = *(uint32_t*)hp;
                *(uint32_t*)(ol + addr) = *(uint32_t*)lp;
            }
        }
    }
}

// ---------------------------------------------------------------------------
// Phase 2: scores via HMMA bf16x3, K rows gathered on-load via g_cols
// (no separate gather kernel). Dead k-tiles exit immediately.
// ---------------------------------------------------------------------------
#define SC_SM_Q (128 * RP)
#define SC_SM_K (256 * RP)
#define SC_COLS_OFF (2 * SC_SM_Q + 2 * SC_SM_K)     // bf16-elem offset
#define SC_SM_BYTES (SC_COLS_OFF * 2 + 512)

__global__ void __launch_bounds__(512, 1) scores_mma_kernel()
{
    extern __shared__ __nv_bfloat16 sm[];
    __nv_bfloat16* sQh = sm;
    __nv_bfloat16* sQl = sm + SC_SM_Q;
    __nv_bfloat16* sKh = sm + 2 * SC_SM_Q;
    __nv_bfloat16* sKl = sm + 2 * SC_SM_Q + SC_SM_K;
    unsigned short* scols = (unsigned short*)(sm + SC_COLS_OFF);

    int kt = blockIdx.x, qt = blockIdx.y, bh = blockIdx.z;
    int b = bh / H, h = bh % H;

    if (kt * 256 >= g_nv[b]) return;      // dead tile: all columns masked

    int tid = threadIdx.x;
    int wid = tid >> 5, lane = tid & 31;

    if (tid < 256) scols[tid] = g_cols[b][kt * 256 + tid];
    __syncthreads();

    {
        const __nv_bfloat16* qhb = g_qh + (size_t)(b * L + qt * 128) * D + h * DK;
        const __nv_bfloat16* qlb = g_ql + (size_t)(b * L + qt * 128) * D + h * DK;
        const __nv_bfloat16* khb = g_kh + (size_t)(b * L) * D + h * DK;
        const __nv_bfloat16* klb = g_kl + (size_t)(b * L) * D + h * DK;

        #pragma unroll
        for (int it = 0; it < 2; it++) {
            int idx = tid + it * 512;
            int row = idx >> 3;
            int c8  = (idx & 7) * 8;
            *(uint4*)(sQh + row * RP + c8) = *(const uint4*)(qhb + (size_t)row * D + c8);
            *(uint4*)(sQl + row * RP + c8) = *(const uint4*)(qlb + (size_t)row * D + c8);
        }
        #pragma unroll
        for (int it = 0; it < 4; it++) {
            int idx = tid + it * 512;
            int row = idx >> 3;
            int c8  = (idx & 7) * 8;
            int srow = scols[row];                   // gathered source row
            *(uint4*)(sKh + row * RP + c8) = *(const uint4*)(khb + (size_t)srow * D + c8);
            *(uint4*)(sKl + row * RP + c8) = *(const uint4*)(klb + (size_t)srow * D + c8);
        }
    }
    __syncthreads();

    int wm = (wid & 1) * 64;
    int wn = (wid >> 1) * 32;

    float acc[4][4][4];
    #pragma unroll
    for (int i = 0; i < 4; i++)
        #pragma unroll
        for (int j = 0; j < 4; j++)
            #pragma unroll
            for (int r = 0; r < 4; r++) acc[i][j][r] = 0.f;

    uint32_t sQh_b = smem_u32(sQh), sQl_b = smem_u32(sQl);
    uint32_t sKh_b = smem_u32(sKh), sKl_b = smem_u32(sKl);

    int a_row = lane & 15;
    int a_kh8 = (lane >> 4) * 8;
    int b_row = lane & 7;
    int b_kh8 = ((lane >> 3) & 1) * 8;

    #pragma unroll
    for (int ks = 0; ks < 4; ks++) {
        int kb = ks * 16;
        uint32_t ah[4][4], al[4][4];
        #pragma unroll
        for (int i = 0; i < 4; i++) {
            uint32_t off = (uint32_t)((wm + i * 16 + a_row) * RP + kb + a_kh8) * 2;
            ldsm_x4(sQh_b + off, ah[i][0], ah[i][1], ah[i][2], ah[i][3]);
            ldsm_x4(sQl_b + off, al[i][0], al[i][1], al[i][2], al[i][3]);
        }
        #pragma unroll
        for (int j = 0; j < 4; j++) {
            uint32_t off = (uint32_t)((wn + j * 8 + b_row) * RP + kb + b_kh8) * 2;
            uint32_t bh2[2], bl2[2];
            ldsm_x2(sKh_b + off, bh2[0], bh2[1]);
            ldsm_x2(sKl_b + off, bl2[0], bl2[1]);
            #pragma unroll
            for (int i = 0; i < 4; i++) {
                mma_bf16(acc[i][j], ah[i], bh2);
                mma_bf16(acc[i][j], ah[i], bl2);
                mma_bf16(acc[i][j], al[i], bh2);
            }
        }
    }

    const float scale = 1.0f / 16.0f;
    int r0 = lane >> 2;
    int cp = (lane & 3) * 2;
    #pragma unroll
    for (int i = 0; i < 4; i++) {
        int grow0 = qt * 128 + wm + i * 16 + r0;
        #pragma unroll
        for (int j = 0; j < 4; j++) {
            int gcol = kt * 256 + wn + j * 8 + cp;
            float2 v0 = make_float2(acc[i][j][0] * scale, acc[i][j][1] * scale);
            float2 v1 = make_float2(acc[i][j][2] * scale, acc[i][j][3] * scale);
            *(float2*)(g_s + ((size_t)bh * L + grow0) * L + gcol) = v0;
            *(float2*)(g_s + ((size_t)bh * L + grow0 + 8) * L + gcol) = v1;
        }
    }
}

// ---------------------------------------------------------------------------
// Phase 3 (fast path, nv<=1024): entmax-1.5, TWO warps per row (6 heads each),
// partial accs combined via smem. 4 rows per 256-thread block.
// ---------------------------------------------------------------------------
__global__ void __launch_bounds__(256) entmax_dense2_kernel(float* __restrict__ out)
{
    __shared__ float sacc[4][1032];

    int tid = threadIdx.x;
    int w = tid >> 5, lane = tid & 31;
    int rowi = w >> 1;                 // 0..3
    int half = w & 1;                  // 0 or 1
    int gq = blockIdx.x * 4 + rowi;
    int b = gq / L, qi = gq % L;

    int nv = g_nv[b];
    if (nv > 1024) return;             // uniform per block (same b)

    float acc[32];
    #pragma unroll
    for (int e = 0; e < 32; e++) acc[e] = 0.f;

    const float invH = 1.0f / 12.0f;

    for (int hh = 0; hh < 6; hh++) {
        int h = half * 6 + hh;
        const float4* row = (const float4*)(g_s + ((size_t)(b * H + h) * L + qi) * L);
        float z[32];
        float m = -1e30f;
        #pragma unroll
        for (int i = 0; i < 8; i++) {
            int e4 = lane + i * 32;
            float4 v = __ldg(row + e4);
            z[i * 4 + 0] = (4 * e4 + 0 < nv) ? v.x : -1e30f;
            z[i * 4 + 1] = (4 * e4 + 1 < nv) ? v.y : -1e30f;
            z[i * 4 + 2] = (4 * e4 + 2 < nv) ? v.z : -1e30f;
            z[i * 4 + 3] = (4 * e4 + 3 < nv) ? v.w : -1e30f;
            m = fmaxf(m, fmaxf(fmaxf(z[i*4], z[i*4+1]), fmaxf(z[i*4+2], z[i*4+3])));
        }
        #pragma unroll
        for (int o = 16; o; o >>= 1) m = fmaxf(m, __shfl_xor_sync(0xffffffffu, m, o));

        float tau = m - 1.0f;
        const float tmax = m - 1e-7f;

        for (int it = 0; it < 20; it++) {
            float s0 = 0.f, s1 = 0.f;
            #pragma unroll
            for (int e = 0; e < 32; e++) {
                float d = fmaxf(z[e] - tau, 0.f);
                s1 += d;
                s0 = fmaf(d, d, s0);
            }
            #pragma unroll
            for (int o = 16; o; o >>= 1) {
                s0 += __shfl_xor_sync(0xffffffffu, s0, o);
                s1 += __shfl_xor_sync(0xffffffffu, s1, o);
            }
            float step;
            if (s0 > 2.0f) step = (s0 - sqrtf(s0)) / s1;          // Newton on sqrt(f)
            else           step = (s0 - 1.0f) / (2.0f * s1);      // standard Newton
            tau = fminf(tau + step, tmax);
            if (fabsf(step) <= 5e-7f) break;
        }

        #pragma unroll
        for (int e = 0; e < 32; e++) {
            float d = z[e] - tau;
            if (d > 0.f) acc[e] = fmaf(d * d, invH, acc[e]);
        }
    }

    // combine halves through smem
    if (half == 1) {
        #pragma unroll
        for (int i = 0; i < 8; i++) {
            int e4 = lane + i * 32;
            *(float4*)&sacc[rowi][4 * e4] = make_float4(acc[i*4], acc[i*4+1], acc[i*4+2], acc[i*4+3]);
        }
    }
    __syncthreads();
    if (half == 0) {
        float* orow = out + ((size_t)b * L + qi) * L;
        #pragma unroll
        for (int i = 0; i < 12; i++)
            ((float4*)orow)[lane + i * 32] = make_float4(0.f, 0.f, 0.f, 0.f);
        __syncwarp();
        #pragma unroll
        for (int i = 0; i < 8; i++) {
            int e4 = lane + i * 32;
            float4 o = *(const float4*)&sacc[rowi][4 * e4];
            float p0 = acc[i*4+0] + o.x;
            float p1 = acc[i*4+1] + o.y;
            float p2 = acc[i*4+2] + o.z;
            float p3 = acc[i*4+3] + o.w;
            if (4 * e4 < nv) {
                ushort4 c4 = *(const ushort4*)&g_cols[b][4 * e4];
                orow[c4.x] = p0;
                if (4 * e4 + 1 < nv) orow[c4.y] = p1;
                if (4 * e4 + 2 < nv) orow[c4.z] = p2;
                if (4 * e4 + 3 < nv) orow[c4.w] = p3;
            }
        }
    }
}

// ---------------------------------------------------------------------------
// Phase 3 (guarded exact fallback, nv>1024): warp per row, C=12.
// ---------------------------------------------------------------------------
__global__ void __launch_bounds__(128) entmax_dense12_kernel(float* __restrict__ out)
{
    int warp = (blockIdx.x * blockDim.x + threadIdx.x) >> 5;
    int lane = threadIdx.x & 31;
    int b = warp / L, qi = warp % L;

    int nv = g_nv[b];
    if (nv <= 1024) return;

    float acc[48];
    #pragma unroll
    for (int e = 0; e < 48; e++) acc[e] = 0.f;

    const float invH = 1.0f / 12.0f;

    for (int h = 0; h < H; h++) {
        const float4* row = (const float4*)(g_s + ((size_t)(b * H + h) * L + qi) * L);
        float z[48];
        float m = -1e30f;
        #pragma unroll
        for (int i = 0; i < 12; i++) {
            int e4 = lane + i * 32;
            float4 v = __ldg(row + e4);
            z[i * 4 + 0] = (4 * e4 + 0 < nv) ? v.x : -1e30f;
            z[i * 4 + 1] = (4 * e4 + 1 < nv) ? v.y : -1e30f;
            z[i * 4 + 2] = (4 * e4 + 2 < nv) ? v.z : -1e30f;
            z[i * 4 + 3] = (4 * e4 + 3 < nv) ? v.w : -1e30f;
            m = fmaxf(m, fmaxf(fmaxf(z[i*4], z[i*4+1]), fmaxf(z[i*4+2], z[i*4+3])));
        }
        #pragma unroll
        for (int o = 16; o; o >>= 1) m = fmaxf(m, __shfl_xor_sync(0xffffffffu, m, o));

        float tau = m - 1.0f;
        const float tmax = m - 1e-7f;

        for (int it = 0; it < 20; it++) {
            float s0 = 0.f, s1 = 0.f;
            #pragma unroll
            for (int e = 0; e < 48; e++) {
                float d = fmaxf(z[e] - tau, 0.f);
                s1 += d;
                s0 = fmaf(d, d, s0);
            }
            #pragma unroll
            for (int o = 16; o; o >>= 1) {
                s0 += __shfl_xor_sync(0xffffffffu, s0, o);
                s1 += __shfl_xor_sync(0xffffffffu, s1, o);
            }
            float step;
            if (s0 > 2.0f) step = (s0 - sqrtf(s0)) / s1;
            else           step = (s0 - 1.0f) / (2.0f * s1);
            tau = fminf(tau + step, tmax);
            if (fabsf(step) <= 5e-7f) break;
        }

        #pragma unroll
        for (int e = 0; e < 48; e++) {
            float d = z[e] - tau;
            if (d > 0.f) acc[e] = fmaf(d * d, invH, acc[e]);
        }
    }

    float* orow = out + ((size_t)b * L + qi) * L;
    #pragma unroll
    for (int i = 0; i < 12; i++)
        ((float4*)orow)[lane + i * 32] = make_float4(0.f, 0.f, 0.f, 0.f);
    __syncwarp();
    #pragma unroll
    for (int i = 0; i < 12; i++) {
        int e4 = lane + i * 32;
        if (4 * e4 < nv) {
            ushort4 c4 = *(const ushort4*)&g_cols[b][4 * e4];
            orow[c4.x] = acc[i * 4 + 0];
            if (4 * e4 + 1 < nv) orow[c4.y] = acc[i * 4 + 1];
            if (4 * e4 + 2 < nv) orow[c4.z] = acc[i * 4 + 2];
            if (4 * e4 + 3 < nv) orow[c4.w] = acc[i * 4 + 3];
        }
    }
}

// ---------------------------------------------------------------------------
extern "C" void kernel_launch(void* const* d_in, const int* in_sizes, int n_in,
                              void* d_out, int out_size)
{
    const float* query = (const float*)d_in[0];
    const float* key   = (const float*)d_in[1];
    const int*   mask  = (const int*)d_in[2];
    const float* wq_w  = (const float*)d_in[3];
    const float* wq_b  = (const float*)d_in[4];
    const float* wk_w  = (const float*)d_in[5];
    const float* wk_b  = (const float*)d_in[6];
    float* out = (float*)d_out;

    (void)in_sizes; (void)n_in; (void)out_size;

    cudaFuncSetAttribute(proj_mma_kernel,
                         cudaFuncAttributeMaxDynamicSharedMemorySize, PROJ_SM_BYTES);
    cudaFuncSetAttribute(scores_mma_kernel,
                         cudaFuncAttributeMaxDynamicSharedMemorySize, SC_SM_BYTES);

    {
        int total4 = (int)(2 * (BLD / 4) + 2 * (DD / 4));
        split_all_kernel<<<(total4 + 255) / 256, 256>>>(query, key, wq_w, wk_w);   // 0
    }
    build_colmap_kernel<<<B, 512>>>(mask);                                          // 1

    dim3 pgrid(D / 256, (B * L) / 128, 2);
    proj_mma_kernel<<<pgrid, 512, PROJ_SM_BYTES>>>(wq_b, wk_b);                     // 2

    dim3 sgrid(L / 256, L / 128, B * H);
    scores_mma_kernel<<<sgrid, 512, SC_SM_BYTES>>>();                               // 3 (captured)

    entmax_dense2_kernel<<<(B * L) / 4, 256>>>(out);                                // 4
    entmax_dense12_kernel<<<(B * L) / 4, 128>>>(out);                               // 5 fallback
}

// round 14
// speedup vs baseline: 1.0095x; 1.0020x over previous
#include <cuda_runtime.h>
#include <cuda_bf16.h>
#include <cstdint>

#define B 2
#define L 1536
#define D 768
#define H 12
#define DK 64
#define BLD ((size_t)B * L * D)
#define DD  ((size_t)D * D)

// ---------------------------------------------------------------------------
// Scratch (allocation-free rule: static __device__ arrays)
// ---------------------------------------------------------------------------
__device__ __nv_bfloat16 g_xqh[BLD], g_xql[BLD];
__device__ __nv_bfloat16 g_xkh[BLD], g_xkl[BLD];
__device__ __nv_bfloat16 g_wqh[DD],  g_wql[DD];
__device__ __nv_bfloat16 g_wkh[DD],  g_wkl[DD];
__device__ __nv_bfloat16 g_qh[BLD], g_ql[BLD];
__device__ __nv_bfloat16 g_kh[BLD], g_kl[BLD];
__device__ float g_s[(size_t)B * H * L * L];       // z, dense-compacted columns

__device__ int            g_nv[B];
__device__ unsigned short g_cols[B][L];            // dense -> col (zero-init tail)

__device__ __forceinline__ uint32_t smem_u32(const void* p) {
    uint32_t a;
    asm("{ .reg .u64 t; cvta.to.shared.u64 t, %1; cvt.u32.u64 %0, t; }" : "=r"(a) : "l"(p));
    return a;
}
__device__ __forceinline__ void ldsm_x4(uint32_t addr, uint32_t& r0, uint32_t& r1,
                                        uint32_t& r2, uint32_t& r3) {
    asm volatile("ldmatrix.sync.aligned.m8n8.x4.shared.b16 {%0,%1,%2,%3}, [%4];"
                 : "=r"(r0), "=r"(r1), "=r"(r2), "=r"(r3) : "r"(addr));
}
__device__ __forceinline__ void ldsm_x2(uint32_t addr, uint32_t& r0, uint32_t& r1) {
    asm volatile("ldmatrix.sync.aligned.m8n8.x2.shared.b16 {%0,%1}, [%2];"
                 : "=r"(r0), "=r"(r1) : "r"(addr));
}
__device__ __forceinline__ void mma_bf16(float* c, const uint32_t* a, const uint32_t* b) {
    asm volatile(
        "mma.sync.aligned.m16n8k16.row.col.f32.bf16.bf16.f32 "
        "{%0,%1,%2,%3}, {%4,%5,%6,%7}, {%8,%9}, {%0,%1,%2,%3};"
        : "+f"(c[0]), "+f"(c[1]), "+f"(c[2]), "+f"(c[3])
        : "r"(a[0]), "r"(a[1]), "r"(a[2]), "r"(a[3]), "r"(b[0]), "r"(b[1]));
}
__device__ __forceinline__ void cpa16(uint32_t s, const void* g) {
    asm volatile("cp.async.cg.shared.global [%0], [%1], 16;" :: "r"(s), "l"(g));
}
#define CPA_COMMIT() asm volatile("cp.async.commit_group;" ::: "memory")
#define CPA_WAIT1()  asm volatile("cp.async.wait_group 1;" ::: "memory")
#define CPA_WAIT0()  asm volatile("cp.async.wait_group 0;" ::: "memory")

// ---------------------------------------------------------------------------
// Phase 0: fp32 -> bf16 hi/lo split of ALL four sources, ONE launch.
// ---------------------------------------------------------------------------
__global__ void split_all_kernel(const float* __restrict__ query,
                                 const float* __restrict__ key,
                                 const float* __restrict__ wq,
                                 const float* __restrict__ wk)
{
    const int n4x = (int)(BLD / 4);
    const int n4w = (int)(DD / 4);
    int i = blockIdx.x * blockDim.x + threadIdx.x;

    const float* src;
    __nv_bfloat16 *dh, *dl;
    int li;
    if (i < 2 * n4x) {
        if (i < n4x) { src = query; dh = g_xqh; dl = g_xql; li = i; }
        else         { src = key;   dh = g_xkh; dl = g_xkl; li = i - n4x; }
    } else {
        int j = i - 2 * n4x;
        if (j >= 2 * n4w) return;
        if (j < n4w) { src = wq; dh = g_wqh; dl = g_wql; li = j; }
        else         { src = wk; dh = g_wkh; dl = g_wkl; li = j - n4w; }
    }

    float4 v = ((const float4*)src)[li];
    __nv_bfloat16 h[4], l[4];
    const float* f = &v.x;
    #pragma unroll
    for (int j = 0; j < 4; j++) {
        h[j] = __float2bfloat16(f[j]);
        l[j] = __float2bfloat16(f[j] - __bfloat162float(h[j]));
    }
    ((uint2*)dh)[li] = *(uint2*)h;
    ((uint2*)dl)[li] = *(uint2*)l;
}

// ---------------------------------------------------------------------------
// Phase 0.5: build column compaction (per batch): nv, cols.
// ---------------------------------------------------------------------------
__global__ void build_colmap_kernel(const int* __restrict__ mask)
{
    int b = blockIdx.x;
    int t = threadIdx.x;
    __shared__ int s[512];

    int m0 = mask[b * L + 3 * t + 0] != 0;
    int m1 = mask[b * L + 3 * t + 1] != 0;
    int m2 = mask[b * L + 3 * t + 2] != 0;
    int cnt = m0 + m1 + m2;
    s[t] = cnt;
    __syncthreads();
    for (int off = 1; off < 512; off <<= 1) {
        int v = (t >= off) ? s[t - off] : 0;
        __syncthreads();
        s[t] += v;
        __syncthreads();
    }
    int d = s[t] - cnt;
    if (t == 511) g_nv[b] = s[511];

    int col = 3 * t;
    if (m0) g_cols[b][d++] = (unsigned short)col;
    col++;
    if (m1) g_cols[b][d++] = (unsigned short)col;
    col++;
    if (m2) g_cols[b][d] = (unsigned short)col;
}

// ---------------------------------------------------------------------------
// Phase 1: projection via HMMA bf16x3, cp.async double-buffered K loop.
// ---------------------------------------------------------------------------
#define RP 72
#define P_AH 0
#define P_AL (128 * RP)
#define P_BH (2 * 128 * RP)
#define P_BL (2 * 128 * RP + 256 * RP)
#define PROJ_BUF (2 * 128 * RP + 2 * 256 * RP)
#define PROJ_SM_BYTES (2 * PROJ_BUF * 2)

__global__ void __launch_bounds__(512, 1) proj_mma_kernel(
    const float* __restrict__ biasq, const float* __restrict__ biask)
{
    extern __shared__ __nv_bfloat16 sm[];
    const uint32_t sm_b = smem_u32(sm);

    int nt = blockIdx.x, mt = blockIdx.y, which = blockIdx.z;
    int tid = threadIdx.x;
    int wid = tid >> 5, lane = tid & 31;

    const __nv_bfloat16* xh = which ? g_xkh : g_xqh;
    const __nv_bfloat16* xl = which ? g_xkl : g_xql;
    const __nv_bfloat16* wh = which ? g_wkh : g_wqh;
    const __nv_bfloat16* wl = which ? g_wkl : g_wql;
    __nv_bfloat16* oh = which ? g_kh : g_qh;
    __nv_bfloat16* ol = which ? g_kl : g_ql;
    const float* bias = which ? biask : biasq;

    int wm = (wid & 1) * 64;
    int wn = (wid >> 1) * 32;

    float acc[4][4][4];
    #pragma unroll
    for (int i = 0; i < 4; i++)
        #pragma unroll
        for (int j = 0; j < 4; j++)
            #pragma unroll
            for (int r = 0; r < 4; r++) acc[i][j][r] = 0.f;

    int a_row = lane & 15;
    int a_kh8 = (lane >> 4) * 8;
    int b_row = lane & 7;
    int b_kh8 = ((lane >> 3) & 1) * 8;

    int lrowA[2], lc8A[2], lrowB[4], lc8B[4];
    #pragma unroll
    for (int it = 0; it < 2; it++) { int idx = tid + it * 512; lrowA[it] = idx >> 3; lc8A[it] = (idx & 7) * 8; }
    #pragma unroll
    for (int it = 0; it < 4; it++) { int idx = tid + it * 512; lrowB[it] = idx >> 3; lc8B[it] = (idx & 7) * 8; }

    auto prefetch = [&](int kc, int pb) {
        uint32_t base = sm_b + (uint32_t)pb * PROJ_BUF * 2;
        #pragma unroll
        for (int it = 0; it < 2; it++) {
            size_t g = (size_t)(mt * 128 + lrowA[it]) * D + kc + lc8A[it];
            uint32_t so = (uint32_t)(lrowA[it] * RP + lc8A[it]) * 2;
            cpa16(base + P_AH * 2 + so, xh + g);
            cpa16(base + P_AL * 2 + so, xl + g);
        }
        #pragma unroll
        for (int it = 0; it < 4; it++) {
            size_t g = (size_t)(nt * 256 + lrowB[it]) * D + kc + lc8B[it];
            uint32_t so = (uint32_t)(lrowB[it] * RP + lc8B[it]) * 2;
            cpa16(base + P_BH * 2 + so, wh + g);
            cpa16(base + P_BL * 2 + so, wl + g);
        }
        CPA_COMMIT();
    };

    prefetch(0, 0);

    int buf = 0;
    for (int kci = 0; kci < 12; kci++) {
        if (kci < 11) { prefetch((kci + 1) * 64, buf ^ 1); CPA_WAIT1(); }
        else          { CPA_WAIT0(); }
        __syncthreads();

        uint32_t base = sm_b + (uint32_t)buf * PROJ_BUF * 2;
        uint32_t sAh_b = base + P_AH * 2, sAl_b = base + P_AL * 2;
        uint32_t sBh_b = base + P_BH * 2, sBl_b = base + P_BL * 2;

        #pragma unroll
        for (int ks = 0; ks < 4; ks++) {
            int kb = ks * 16;
            uint32_t ah[4][4], al[4][4];
            #pragma unroll
            for (int i = 0; i < 4; i++) {
                uint32_t off = (uint32_t)((wm + i * 16 + a_row) * RP + kb + a_kh8) * 2;
                ldsm_x4(sAh_b + off, ah[i][0], ah[i][1], ah[i][2], ah[i][3]);
                ldsm_x4(sAl_b + off, al[i][0], al[i][1], al[i][2], al[i][3]);
            }
            #pragma unroll
            for (int j = 0; j < 4; j++) {
                uint32_t off = (uint32_t)((wn + j * 8 + b_row) * RP + kb + b_kh8) * 2;
                uint32_t bh[2], bl[2];
                ldsm_x2(sBh_b + off, bh[0], bh[1]);
                ldsm_x2(sBl_b + off, bl[0], bl[1]);
                #pragma unroll
                for (int i = 0; i < 4; i++) {
                    mma_bf16(acc[i][j], ah[i], bh);
                    mma_bf16(acc[i][j], ah[i], bl);
                    mma_bf16(acc[i][j], al[i], bh);
                }
            }
        }
        __syncthreads();
        buf ^= 1;
    }

    int r0 = lane >> 2;
    int cp = (lane & 3) * 2;
    #pragma unroll
    for (int i = 0; i < 4; i++) {
        int grow0 = mt * 128 + wm + i * 16 + r0;
        #pragma unroll
        for (int j = 0; j < 4; j++) {
            int gcol = nt * 256 + wn + j * 8 + cp;
            float2 bv = *(const float2*)(bias + gcol);
            #pragma unroll
            for (int half = 0; half < 2; half++) {
                float v0 = acc[i][j][half * 2 + 0] + bv.x;
                float v1 = acc[i][j][half * 2 + 1] + bv.y;
                __nv_bfloat16 h0 = __float2bfloat16(v0);
                __nv_bfloat16 h1 = __float2bfloat16(v1);
                __nv_bfloat16 l0 = __float2bfloat16(v0 - __bfloat162float(h0));
                __nv_bfloat16 l1 = __float2bfloat16(v1 - __bfloat162float(h1));
                size_t addr = (size_t)(grow0 + half * 8) * D + gcol;
                __nv_bfloat16 hp[2] = {h0, h1}, lp[2] = {l0, l1};
                *(uint32_t*)(oh + addr) = *(uint32_t*)hp;
                *(uint32_t*)(ol + addr) = *(uint32_t*)lp;
            }
        }
    }
}

// ---------------------------------------------------------------------------
// Phase 2: scores via HMMA bf16x3, K rows gathered on-load via g_cols
// (no separate gather kernel). Dead k-tiles exit immediately.
// ---------------------------------------------------------------------------
#define SC_SM_Q (128 * RP)
#define SC_SM_K (256 * RP)
#define SC_COLS_OFF (2 * SC_SM_Q + 2 * SC_SM_K)     // bf16-elem offset
#define SC_SM_BYTES (SC_COLS_OFF * 2 + 512)

__global__ void __launch_bounds__(512, 1) scores_mma_kernel()
{
    extern __shared__ __nv_bfloat16 sm[];
    __nv_bfloat16* sQh = sm;
    __nv_bfloat16* sQl = sm + SC_SM_Q;
    __nv_bfloat16* sKh = sm + 2 * SC_SM_Q;
    __nv_bfloat16* sKl = sm + 2 * SC_SM_Q + SC_SM_K;
    unsigned short* scols = (unsigned short*)(sm + SC_COLS_OFF);

    int kt = blockIdx.x, qt = blockIdx.y, bh = blockIdx.z;
    int b = bh / H, h = bh % H;

    if (kt * 256 >= g_nv[b]) return;      // dead tile: all columns masked

    int tid = threadIdx.x;
    int wid = tid >> 5, lane = tid & 31;

    if (tid < 256) scols[tid] = g_cols[b][kt * 256 + tid];
    __syncthreads();

    {
        const __nv_bfloat16* qhb = g_qh + (size_t)(b * L + qt * 128) * D + h * DK;
        const __nv_bfloat16* qlb = g_ql + (size_t)(b * L + qt * 128) * D + h * DK;
        const __nv_bfloat16* khb = g_kh + (size_t)(b * L) * D + h * DK;
        const __nv_bfloat16* klb = g_kl + (size_t)(b * L) * D + h * DK;

        #pragma unroll
        for (int it = 0; it < 2; it++) {
            int idx = tid + it * 512;
            int row = idx >> 3;
            int c8  = (idx & 7) * 8;
            *(uint4*)(sQh + row * RP + c8) = *(const uint4*)(qhb + (size_t)row * D + c8);
            *(uint4*)(sQl + row * RP + c8) = *(const uint4*)(qlb + (size_t)row * D + c8);
        }
        #pragma unroll
        for (int it = 0; it < 4; it++) {
            int idx = tid + it * 512;
            int row = idx >> 3;
            int c8  = (idx & 7) * 8;
            int srow = scols[row];                   // gathered source row
            *(uint4*)(sKh + row * RP + c8) = *(const uint4*)(khb + (size_t)srow * D + c8);
            *(uint4*)(sKl + row * RP + c8) = *(const uint4*)(klb + (size_t)srow * D + c8);
        }
    }
    __syncthreads();

    int wm = (wid & 1) * 64;
    int wn = (wid >> 1) * 32;

    float acc[4][4][4];
    #pragma unroll
    for (int i = 0; i < 4; i++)
        #pragma unroll
        for (int j = 0; j < 4; j++)
            #pragma unroll
            for (int r = 0; r < 4; r++) acc[i][j][r] = 0.f;

    uint32_t sQh_b = smem_u32(sQh), sQl_b = smem_u32(sQl);
    uint32_t sKh_b = smem_u32(sKh), sKl_b = smem_u32(sKl);

    int a_row = lane & 15;
    int a_kh8 = (lane >> 4) * 8;
    int b_row = lane & 7;
    int b_kh8 = ((lane >> 3) & 1) * 8;

    #pragma unroll
    for (int ks = 0; ks < 4; ks++) {
        int kb = ks * 16;
        uint32_t ah[4][4], al[4][4];
        #pragma unroll
        for (int i = 0; i < 4; i++) {
            uint32_t off = (uint32_t)((wm + i * 16 + a_row) * RP + kb + a_kh8) * 2;
            ldsm_x4(sQh_b + off, ah[i][0], ah[i][1], ah[i][2], ah[i][3]);
            ldsm_x4(sQl_b + off, al[i][0], al[i][1], al[i][2], al[i][3]);
        }
        #pragma unroll
        for (int j = 0; j < 4; j++) {
            uint32_t off = (uint32_t)((wn + j * 8 + b_row) * RP + kb + b_kh8) * 2;
            uint32_t bh2[2], bl2[2];
            ldsm_x2(sKh_b + off, bh2[0], bh2[1]);
            ldsm_x2(sKl_b + off, bl2[0], bl2[1]);
            #pragma unroll
            for (int i = 0; i < 4; i++) {
                mma_bf16(acc[i][j], ah[i], bh2);
                mma_bf16(acc[i][j], ah[i], bl2);
                mma_bf16(acc[i][j], al[i], bh2);
            }
        }
    }

    const float scale = 1.0f / 16.0f;
    int r0 = lane >> 2;
    int cp = (lane & 3) * 2;
    #pragma unroll
    for (int i = 0; i < 4; i++) {
        int grow0 = qt * 128 + wm + i * 16 + r0;
        #pragma unroll
        for (int j = 0; j < 4; j++) {
            int gcol = kt * 256 + wn + j * 8 + cp;
            float2 v0 = make_float2(acc[i][j][0] * scale, acc[i][j][1] * scale);
            float2 v1 = make_float2(acc[i][j][2] * scale, acc[i][j][3] * scale);
            *(float2*)(g_s + ((size_t)bh * L + grow0) * L + gcol) = v0;
            *(float2*)(g_s + ((size_t)bh * L + grow0 + 8) * L + gcol) = v1;
        }
    }
}

// ---------------------------------------------------------------------------
// Phase 3 (fast path, nv<=1024): entmax-1.5, TWO warps per row (6 heads each),
// partial accs combined via smem. 4 rows per 256-thread block.
// ---------------------------------------------------------------------------
__global__ void __launch_bounds__(256) entmax_dense2_kernel(float* __restrict__ out)
{
    __shared__ float sacc[4][1032];

    int tid = threadIdx.x;
    int w = tid >> 5, lane = tid & 31;
    int rowi = w >> 1;                 // 0..3
    int half = w & 1;                  // 0 or 1
    int gq = blockIdx.x * 4 + rowi;
    int b = gq / L, qi = gq % L;

    int nv = g_nv[b];
    if (nv > 1024) return;             // uniform per block (same b)

    float acc[32];
    #pragma unroll
    for (int e = 0; e < 32; e++) acc[e] = 0.f;

    const float invH = 1.0f / 12.0f;

    for (int hh = 0; hh < 6; hh++) {
        int h = half * 6 + hh;
        const float4* row = (const float4*)(g_s + ((size_t)(b * H + h) * L + qi) * L);
        float z[32];
        float m = -1e30f;
        #pragma unroll
        for (int i = 0; i < 8; i++) {
            int e4 = lane + i * 32;
            float4 v = __ldg(row + e4);
            z[i * 4 + 0] = (4 * e4 + 0 < nv) ? v.x : -1e30f;
            z[i * 4 + 1] = (4 * e4 + 1 < nv) ? v.y : -1e30f;
            z[i * 4 + 2] = (4 * e4 + 2 < nv) ? v.z : -1e30f;
            z[i * 4 + 3] = (4 * e4 + 3 < nv) ? v.w : -1e30f;
            m = fmaxf(m, fmaxf(fmaxf(z[i*4], z[i*4+1]), fmaxf(z[i*4+2], z[i*4+3])));
        }
        #pragma unroll
        for (int o = 16; o; o >>= 1) m = fmaxf(m, __shfl_xor_sync(0xffffffffu, m, o));

        float tau = m - 1.0f;
        const float tmax = m - 1e-7f;

        for (int it = 0; it < 20; it++) {
            float s0 = 0.f, s1 = 0.f;
            #pragma unroll
            for (int e = 0; e < 32; e++) {
                float d = fmaxf(z[e] - tau, 0.f);
                s1 += d;
                s0 = fmaf(d, d, s0);
            }
            #pragma unroll
            for (int o = 16; o; o >>= 1) {
                s0 += __shfl_xor_sync(0xffffffffu, s0, o);
                s1 += __shfl_xor_sync(0xffffffffu, s1, o);
            }
            float step;
            if (s0 > 2.0f) step = (s0 - sqrtf(s0)) / s1;          // Newton on sqrt(f)
            else           step = (s0 - 1.0f) / (2.0f * s1);      // standard Newton
            tau = fminf(tau + step, tmax);
            if (fabsf(step) <= 5e-7f) break;
        }

        #pragma unroll
        for (int e = 0; e < 32; e++) {
            float d = z[e] - tau;
            if (d > 0.f) acc[e] = fmaf(d * d, invH, acc[e]);
        }
    }

    // combine halves through smem
    if (half == 1) {
        #pragma unroll
        for (int i = 0; i < 8; i++) {
            int e4 = lane + i * 32;
            *(float4*)&sacc[rowi][4 * e4] = make_float4(acc[i*4], acc[i*4+1], acc[i*4+2], acc[i*4+3]);
        }
    }
    __syncthreads();
    if (half == 0) {
        float* orow = out + ((size_t)b * L + qi) * L;
        #pragma unroll
        for (int i = 0; i < 12; i++)
            ((float4*)orow)[lane + i * 32] = make_float4(0.f, 0.f, 0.f, 0.f);
        __syncwarp();
        #pragma unroll
        for (int i = 0; i < 8; i++) {
            int e4 = lane + i * 32;
            float4 o = *(const float4*)&sacc[rowi][4 * e4];
            float p0 = acc[i*4+0] + o.x;
            float p1 = acc[i*4+1] + o.y;
            float p2 = acc[i*4+2] + o.z;
            float p3 = acc[i*4+3] + o.w;
            if (4 * e4 < nv) {
                ushort4 c4 = *(const ushort4*)&g_cols[b][4 * e4];
                orow[c4.x] = p0;
                if (4 * e4 + 1 < nv) orow[c4.y] = p1;
                if (4 * e4 + 2 < nv) orow[c4.z] = p2;
                if (4 * e4 + 3 < nv) orow[c4.w] = p3;
            }
        }
    }
}

// ---------------------------------------------------------------------------
// Phase 3 (guarded exact fallback, nv>1024): warp per row, C=12.
// ---------------------------------------------------------------------------
__global__ void __launch_bounds__(128) entmax_dense12_kernel(float* __restrict__ out)
{
    int warp = (blockIdx.x * blockDim.x + threadIdx.x) >> 5;
    int lane = threadIdx.x & 31;
    int b = warp / L, qi = warp % L;

    int nv = g_nv[b];
    if (nv <= 1024) return;

    float acc[48];
    #pragma unroll
    for (int e = 0; e < 48; e++) acc[e] = 0.f;

    const float invH = 1.0f / 12.0f;

    for (int h = 0; h < H; h++) {
        const float4* row = (const float4*)(g_s + ((size_t)(b * H + h) * L + qi) * L);
        float z[48];
        float m = -1e30f;
        #pragma unroll
        for (int i = 0; i < 12; i++) {
            int e4 = lane + i * 32;
            float4 v = __ldg(row + e4);
            z[i * 4 + 0] = (4 * e4 + 0 < nv) ? v.x : -1e30f;
            z[i * 4 + 1] = (4 * e4 + 1 < nv) ? v.y : -1e30f;
            z[i * 4 + 2] = (4 * e4 + 2 < nv) ? v.z : -1e30f;
            z[i * 4 + 3] = (4 * e4 + 3 < nv) ? v.w : -1e30f;
            m = fmaxf(m, fmaxf(fmaxf(z[i*4], z[i*4+1]), fmaxf(z[i*4+2], z[i*4+3])));
        }
        #pragma unroll
        for (int o = 16; o; o >>= 1) m = fmaxf(m, __shfl_xor_sync(0xffffffffu, m, o));

        float tau = m - 1.0f;
        const float tmax = m - 1e-7f;

        for (int it = 0; it < 20; it++) {
            float s0 = 0.f, s1 = 0.f;
            #pragma unroll
            for (int e = 0; e < 48; e++) {
                float d = fmaxf(z[e] - tau, 0.f);
                s1 += d;
                s0 = fmaf(d, d, s0);
            }
            #pragma unroll
            for (int o = 16; o; o >>= 1) {
                s0 += __shfl_xor_sync(0xffffffffu, s0, o);
                s1 += __shfl_xor_sync(0xffffffffu, s1, o);
            }
            float step;
            if (s0 > 2.0f) step = (s0 - sqrtf(s0)) / s1;
            else           step = (s0 - 1.0f) / (2.0f * s1);
            tau = fminf(tau + step, tmax);
            if (fabsf(step) <= 5e-7f) break;
        }

        #pragma unroll
        for (int e = 0; e < 48; e++) {
            float d = z[e] - tau;
            if (d > 0.f) acc[e] = fmaf(d * d, invH, acc[e]);
        }
    }

    float* orow = out + ((size_t)b * L + qi) * L;
    #pragma unroll
    for (int i = 0; i < 12; i++)
        ((float4*)orow)[lane + i * 32] = make_float4(0.f, 0.f, 0.f, 0.f);
    __syncwarp();
    #pragma unroll
    for (int i = 0; i < 12; i++) {
        int e4 = lane + i * 32;
        if (4 * e4 < nv) {
            ushort4 c4 = *(const ushort4*)&g_cols[b][4 * e4];
            orow[c4.x] = acc[i * 4 + 0];
            if (4 * e4 + 1 < nv) orow[c4.y] = acc[i * 4 + 1];
            if (4 * e4 + 2 < nv) orow[c4.z] = acc[i * 4 + 2];
            if (4 * e4 + 3 < nv) orow[c4.w] = acc[i * 4 + 3];
        }
    }
}

// ---------------------------------------------------------------------------
extern "C" void kernel_launch(void* const* d_in, const int* in_sizes, int n_in,
                              void* d_out, int out_size)
{
    const float* query = (const float*)d_in[0];
    const float* key   = (const float*)d_in[1];
    const int*   mask  = (const int*)d_in[2];
    const float* wq_w  = (const float*)d_in[3];
    const float* wq_b  = (const float*)d_in[4];
    const float* wk_w  = (const float*)d_in[5];
    const float* wk_b  = (const float*)d_in[6];
    float* out = (float*)d_out;

    (void)in_sizes; (void)n_in; (void)out_size;

    cudaFuncSetAttribute(proj_mma_kernel,
                         cudaFuncAttributeMaxDynamicSharedMemorySize, PROJ_SM_BYTES);
    cudaFuncSetAttribute(scores_mma_kernel,
                         cudaFuncAttributeMaxDynamicSharedMemorySize, SC_SM_BYTES);

    {
        int total4 = (int)(2 * (BLD / 4) + 2 * (DD / 4));
        split_all_kernel<<<(total4 + 255) / 256, 256>>>(query, key, wq_w, wk_w);   // 0
    }
    build_colmap_kernel<<<B, 512>>>(mask);                                          // 1

    dim3 pgrid(D / 256, (B * L) / 128, 2);
    proj_mma_kernel<<<pgrid, 512, PROJ_SM_BYTES>>>(wq_b, wk_b);                     // 2

    dim3 sgrid(L / 256, L / 128, B * H);
    scores_mma_kernel<<<sgrid, 512, SC_SM_BYTES>>>();                               // 3 (captured)

    entmax_dense2_kernel<<<(B * L) / 4, 256>>>(out);                                // 4
    entmax_dense12_kernel<<<(B * L) / 4, 128>>>(out);                               // 5 fallback
}

// round 15
// speedup vs baseline: 1.0589x; 1.0488x over previous
#include <cuda_runtime.h>
#include <cuda_bf16.h>
#include <cstdint>

#define B 2
#define L 1536
#define D 768
#define H 12
#define DK 64
#define BLD ((size_t)B * L * D)
#define DD  ((size_t)D * D)

// ---------------------------------------------------------------------------
// Scratch (allocation-free rule: static __device__ arrays)
// ---------------------------------------------------------------------------
__device__ __nv_bfloat16 g_xqh[BLD], g_xql[BLD];
__device__ __nv_bfloat16 g_xkh[BLD], g_xkl[BLD];
__device__ __nv_bfloat16 g_wqh[DD],  g_wql[DD];
__device__ __nv_bfloat16 g_wkh[DD],  g_wkl[DD];
__device__ __nv_bfloat16 g_qh[BLD], g_ql[BLD];
__device__ __nv_bfloat16 g_kh[BLD], g_kl[BLD];
__device__ float g_s[(size_t)B * H * L * L];       // z, dense-compacted columns

__device__ int            g_nv[B];
__device__ unsigned short g_cols[B][L];            // dense -> col (zero-init tail)

__device__ __forceinline__ uint32_t smem_u32(const void* p) {
    uint32_t a;
    asm("{ .reg .u64 t; cvta.to.shared.u64 t, %1; cvt.u32.u64 %0, t; }" : "=r"(a) : "l"(p));
    return a;
}
__device__ __forceinline__ void ldsm_x4(uint32_t addr, uint32_t& r0, uint32_t& r1,
                                        uint32_t& r2, uint32_t& r3) {
    asm volatile("ldmatrix.sync.aligned.m8n8.x4.shared.b16 {%0,%1,%2,%3}, [%4];"
                 : "=r"(r0), "=r"(r1), "=r"(r2), "=r"(r3) : "r"(addr));
}
__device__ __forceinline__ void ldsm_x2(uint32_t addr, uint32_t& r0, uint32_t& r1) {
    asm volatile("ldmatrix.sync.aligned.m8n8.x2.shared.b16 {%0,%1}, [%2];"
                 : "=r"(r0), "=r"(r1) : "r"(addr));
}
__device__ __forceinline__ void mma_bf16(float* c, const uint32_t* a, const uint32_t* b) {
    asm volatile(
        "mma.sync.aligned.m16n8k16.row.col.f32.bf16.bf16.f32 "
        "{%0,%1,%2,%3}, {%4,%5,%6,%7}, {%8,%9}, {%0,%1,%2,%3};"
        : "+f"(c[0]), "+f"(c[1]), "+f"(c[2]), "+f"(c[3])
        : "r"(a[0]), "r"(a[1]), "r"(a[2]), "r"(a[3]), "r"(b[0]), "r"(b[1]));
}
__device__ __forceinline__ void cpa16(uint32_t s, const void* g) {
    asm volatile("cp.async.cg.shared.global [%0], [%1], 16;" :: "r"(s), "l"(g));
}
#define CPA_COMMIT() asm volatile("cp.async.commit_group;" ::: "memory")
#define CPA_WAIT1()  asm volatile("cp.async.wait_group 1;" ::: "memory")
#define CPA_WAIT0()  asm volatile("cp.async.wait_group 0;" ::: "memory")

// ---------------------------------------------------------------------------
// Phase 0 (merged): split of all four sources + colmap build, ONE launch.
// Blocks [0, nsplit): split (512 thr, one float4 each).
// Blocks [nsplit, nsplit+B): colmap scan for batch (blockIdx.x - nsplit).
// ---------------------------------------------------------------------------
__global__ void __launch_bounds__(512) prep_kernel(
    const float* __restrict__ query, const float* __restrict__ key,
    const float* __restrict__ wq,    const float* __restrict__ wk,
    const int* __restrict__ mask,    int nsplit)
{
    if ((int)blockIdx.x >= nsplit) {
        // ---- colmap for batch b ----
        int b = blockIdx.x - nsplit;
        int t = threadIdx.x;
        __shared__ int s[512];

        int m0 = mask[b * L + 3 * t + 0] != 0;
        int m1 = mask[b * L + 3 * t + 1] != 0;
        int m2 = mask[b * L + 3 * t + 2] != 0;
        int cnt = m0 + m1 + m2;
        s[t] = cnt;
        __syncthreads();
        for (int off = 1; off < 512; off <<= 1) {
            int v = (t >= off) ? s[t - off] : 0;
            __syncthreads();
            s[t] += v;
            __syncthreads();
        }
        int d = s[t] - cnt;
        if (t == 511) g_nv[b] = s[511];

        int col = 3 * t;
        if (m0) g_cols[b][d++] = (unsigned short)col;
        col++;
        if (m1) g_cols[b][d++] = (unsigned short)col;
        col++;
        if (m2) g_cols[b][d] = (unsigned short)col;
        return;
    }

    // ---- split ----
    const int n4x = (int)(BLD / 4);
    const int n4w = (int)(DD / 4);
    int i = blockIdx.x * 512 + threadIdx.x;

    const float* src;
    __nv_bfloat16 *dh, *dl;
    int li;
    if (i < 2 * n4x) {
        if (i < n4x) { src = query; dh = g_xqh; dl = g_xql; li = i; }
        else         { src = key;   dh = g_xkh; dl = g_xkl; li = i - n4x; }
    } else {
        int j = i - 2 * n4x;
        if (j >= 2 * n4w) return;
        if (j < n4w) { src = wq; dh = g_wqh; dl = g_wql; li = j; }
        else         { src = wk; dh = g_wkh; dl = g_wkl; li = j - n4w; }
    }

    float4 v = ((const float4*)src)[li];
    __nv_bfloat16 h[4], l[4];
    const float* f = &v.x;
    #pragma unroll
    for (int j = 0; j < 4; j++) {
        h[j] = __float2bfloat16(f[j]);
        l[j] = __float2bfloat16(f[j] - __bfloat162float(h[j]));
    }
    ((uint2*)dh)[li] = *(uint2*)h;
    ((uint2*)dl)[li] = *(uint2*)l;
}

// ---------------------------------------------------------------------------
// Phase 1: projection via HMMA bf16x3, cp.async double-buffered K loop.
// ---------------------------------------------------------------------------
#define RP 72
#define P_AH 0
#define P_AL (128 * RP)
#define P_BH (2 * 128 * RP)
#define P_BL (2 * 128 * RP + 256 * RP)
#define PROJ_BUF (2 * 128 * RP + 2 * 256 * RP)
#define PROJ_SM_BYTES (2 * PROJ_BUF * 2)

__global__ void __launch_bounds__(512, 1) proj_mma_kernel(
    const float* __restrict__ biasq, const float* __restrict__ biask)
{
    extern __shared__ __nv_bfloat16 sm[];
    const uint32_t sm_b = smem_u32(sm);

    int nt = blockIdx.x, mt = blockIdx.y, which = blockIdx.z;
    int tid = threadIdx.x;
    int wid = tid >> 5, lane = tid & 31;

    const __nv_bfloat16* xh = which ? g_xkh : g_xqh;
    const __nv_bfloat16* xl = which ? g_xkl : g_xql;
    const __nv_bfloat16* wh = which ? g_wkh : g_wqh;
    const __nv_bfloat16* wl = which ? g_wkl : g_wql;
    __nv_bfloat16* oh = which ? g_kh : g_qh;
    __nv_bfloat16* ol = which ? g_kl : g_ql;
    const float* bias = which ? biask : biasq;

    int wm = (wid & 1) * 64;
    int wn = (wid >> 1) * 32;

    float acc[4][4][4];
    #pragma unroll
    for (int i = 0; i < 4; i++)
        #pragma unroll
        for (int j = 0; j < 4; j++)
            #pragma unroll
            for (int r = 0; r < 4; r++) acc[i][j][r] = 0.f;

    int a_row = lane & 15;
    int a_kh8 = (lane >> 4) * 8;
    int b_row = lane & 7;
    int b_kh8 = ((lane >> 3) & 1) * 8;

    int lrowA[2], lc8A[2], lrowB[4], lc8B[4];
    #pragma unroll
    for (int it = 0; it < 2; it++) { int idx = tid + it * 512; lrowA[it] = idx >> 3; lc8A[it] = (idx & 7) * 8; }
    #pragma unroll
    for (int it = 0; it < 4; it++) { int idx = tid + it * 512; lrowB[it] = idx >> 3; lc8B[it] = (idx & 7) * 8; }

    auto prefetch = [&](int kc, int pb) {
        uint32_t base = sm_b + (uint32_t)pb * PROJ_BUF * 2;
        #pragma unroll
        for (int it = 0; it < 2; it++) {
            size_t g = (size_t)(mt * 128 + lrowA[it]) * D + kc + lc8A[it];
            uint32_t so = (uint32_t)(lrowA[it] * RP + lc8A[it]) * 2;
            cpa16(base + P_AH * 2 + so, xh + g);
            cpa16(base + P_AL * 2 + so, xl + g);
        }
        #pragma unroll
        for (int it = 0; it < 4; it++) {
            size_t g = (size_t)(nt * 256 + lrowB[it]) * D + kc + lc8B[it];
            uint32_t so = (uint32_t)(lrowB[it] * RP + lc8B[it]) * 2;
            cpa16(base + P_BH * 2 + so, wh + g);
            cpa16(base + P_BL * 2 + so, wl + g);
        }
        CPA_COMMIT();
    };

    prefetch(0, 0);

    int buf = 0;
    for (int kci = 0; kci < 12; kci++) {
        if (kci < 11) { prefetch((kci + 1) * 64, buf ^ 1); CPA_WAIT1(); }
        else          { CPA_WAIT0(); }
        __syncthreads();

        uint32_t base = sm_b + (uint32_t)buf * PROJ_BUF * 2;
        uint32_t sAh_b = base + P_AH * 2, sAl_b = base + P_AL * 2;
        uint32_t sBh_b = base + P_BH * 2, sBl_b = base + P_BL * 2;

        #pragma unroll
        for (int ks = 0; ks < 4; ks++) {
            int kb = ks * 16;
            uint32_t ah[4][4], al[4][4];
            #pragma unroll
            for (int i = 0; i < 4; i++) {
                uint32_t off = (uint32_t)((wm + i * 16 + a_row) * RP + kb + a_kh8) * 2;
                ldsm_x4(sAh_b + off, ah[i][0], ah[i][1], ah[i][2], ah[i][3]);
                ldsm_x4(sAl_b + off, al[i][0], al[i][1], al[i][2], al[i][3]);
            }
            #pragma unroll
            for (int j = 0; j < 4; j++) {
                uint32_t off = (uint32_t)((wn + j * 8 + b_row) * RP + kb + b_kh8) * 2;
                uint32_t bh[2], bl[2];
                ldsm_x2(sBh_b + off, bh[0], bh[1]);
                ldsm_x2(sBl_b + off, bl[0], bl[1]);
                #pragma unroll
                for (int i = 0; i < 4; i++) {
                    mma_bf16(acc[i][j], ah[i], bh);
                    mma_bf16(acc[i][j], ah[i], bl);
                    mma_bf16(acc[i][j], al[i], bh);
                }
            }
        }
        __syncthreads();
        buf ^= 1;
    }

    int r0 = lane >> 2;
    int cp = (lane & 3) * 2;
    #pragma unroll
    for (int i = 0; i < 4; i++) {
        int grow0 = mt * 128 + wm + i * 16 + r0;
        #pragma unroll
        for (int j = 0; j < 4; j++) {
            int gcol = nt * 256 + wn + j * 8 + cp;
            float2 bv = *(const float2*)(bias + gcol);
            #pragma unroll
            for (int half = 0; half < 2; half++) {
                float v0 = acc[i][j][half * 2 + 0] + bv.x;
                float v1 = acc[i][j][half * 2 + 1] + bv.y;
                __nv_bfloat16 h0 = __float2bfloat16(v0);
                __nv_bfloat16 h1 = __float2bfloat16(v1);
                __nv_bfloat16 l0 = __float2bfloat16(v0 - __bfloat162float(h0));
                __nv_bfloat16 l1 = __float2bfloat16(v1 - __bfloat162float(h1));
                size_t addr = (size_t)(grow0 + half * 8) * D + gcol;
                __nv_bfloat16 hp[2] = {h0, h1}, lp[2] = {l0, l1};
                *(uint32_t*)(oh + addr) = *(uint32_t*)hp;
                *(uint32_t*)(ol + addr) = *(uint32_t*)lp;
            }
        }
    }
}

// ---------------------------------------------------------------------------
// Phase 2: scores via HMMA bf16x3 — k-loop pipelined version.
// Grid (qt 12, bh 24). Q tile loaded once; gathered K tiles double-buffered
// via cp.async; loop over live k-tiles only (ceil(nv/256)).
// ---------------------------------------------------------------------------
#define SC_Q_H  0
#define SC_Q_L  (128 * RP)
#define SC_QSZ  (2 * 128 * RP)                 // Q elems (hi+lo)
#define SC_KBUF (2 * 256 * RP)                  // per K buffer (hi+lo)
#define SC_K0   SC_QSZ
#define SC_K1   (SC_QSZ + SC_KBUF)
#define SC_SM_BYTES ((SC_QSZ + 2 * SC_KBUF) * 2)   // 184,320 B

__global__ void __launch_bounds__(512, 1) scores_mma_kernel()
{
    extern __shared__ __nv_bfloat16 sm[];
    const uint32_t sm_b = smem_u32(sm);

    int qt = blockIdx.x, bh = blockIdx.y;
    int b = bh / H, h = bh % H;
    int nv = g_nv[b];
    int nkt = (nv + 255) >> 8;                 // live k-tiles

    int tid = threadIdx.x;
    int wid = tid >> 5, lane = tid & 31;

    const __nv_bfloat16* khb = g_kh + (size_t)(b * L) * D + h * DK;
    const __nv_bfloat16* klb = g_kl + (size_t)(b * L) * D + h * DK;

    // ---- load Q tile once (regular loads) ----
    {
        const __nv_bfloat16* qhb = g_qh + (size_t)(b * L + qt * 128) * D + h * DK;
        const __nv_bfloat16* qlb = g_ql + (size_t)(b * L + qt * 128) * D + h * DK;
        #pragma unroll
        for (int it = 0; it < 2; it++) {
            int idx = tid + it * 512;
            int row = idx >> 3;
            int c8  = (idx & 7) * 8;
            *(uint4*)(sm + SC_Q_H + row * RP + c8) = *(const uint4*)(qhb + (size_t)row * D + c8);
            *(uint4*)(sm + SC_Q_L + row * RP + c8) = *(const uint4*)(qlb + (size_t)row * D + c8);
        }
    }

    // ---- gathered K tile prefetch via cp.async ----
    auto prefetch = [&](int kt, int pb) {
        uint32_t kbase = sm_b + (uint32_t)(pb ? SC_K1 : SC_K0) * 2;
        #pragma unroll
        for (int it = 0; it < 4; it++) {
            int idx = tid + it * 512;
            int row = idx >> 3;
            int c8  = (idx & 7) * 8;
            int srow = g_cols[b][kt * 256 + row];         // gathered source row
            uint32_t so = (uint32_t)(row * RP + c8) * 2;
            cpa16(kbase + so,                 khb + (size_t)srow * D + c8);
            cpa16(kbase + SC_KBUF / 2 * 2 + so, klb + (size_t)srow * D + c8); // KL at +256*RP elems
        }
        CPA_COMMIT();
    };
    // NOTE: KL offset within buffer = 256*RP elems = SC_KBUF/2

    if (nkt > 0) prefetch(0, 0);

    int a_row = lane & 15;
    int a_kh8 = (lane >> 4) * 8;
    int b_row = lane & 7;
    int b_kh8 = ((lane >> 3) & 1) * 8;

    int wm = (wid & 1) * 64;
    int wn = (wid >> 1) * 32;

    const float scale = 1.0f / 16.0f;
    int r0 = lane >> 2;
    int cp = (lane & 3) * 2;

    uint32_t sQh_b = sm_b + SC_Q_H * 2;
    uint32_t sQl_b = sm_b + SC_Q_L * 2;

    int buf = 0;
    for (int kt = 0; kt < nkt; kt++) {
        if (kt + 1 < nkt) { prefetch(kt + 1, buf ^ 1); CPA_WAIT1(); }
        else              { CPA_WAIT0(); }
        __syncthreads();

        uint32_t sKh_b = sm_b + (uint32_t)(buf ? SC_K1 : SC_K0) * 2;
        uint32_t sKl_b = sKh_b + (uint32_t)(256 * RP) * 2;

        float acc[4][4][4];
        #pragma unroll
        for (int i = 0; i < 4; i++)
            #pragma unroll
            for (int j = 0; j < 4; j++)
                #pragma unroll
                for (int r = 0; r < 4; r++) acc[i][j][r] = 0.f;

        #pragma unroll
        for (int ks = 0; ks < 4; ks++) {
            int kb = ks * 16;
            uint32_t ah[4][4], al[4][4];
            #pragma unroll
            for (int i = 0; i < 4; i++) {
                uint32_t off = (uint32_t)((wm + i * 16 + a_row) * RP + kb + a_kh8) * 2;
                ldsm_x4(sQh_b + off, ah[i][0], ah[i][1], ah[i][2], ah[i][3]);
                ldsm_x4(sQl_b + off, al[i][0], al[i][1], al[i][2], al[i][3]);
            }
            #pragma unroll
            for (int j = 0; j < 4; j++) {
                uint32_t off = (uint32_t)((wn + j * 8 + b_row) * RP + kb + b_kh8) * 2;
                uint32_t bh2[2], bl2[2];
                ldsm_x2(sKh_b + off, bh2[0], bh2[1]);
                ldsm_x2(sKl_b + off, bl2[0], bl2[1]);
                #pragma unroll
                for (int i = 0; i < 4; i++) {
                    mma_bf16(acc[i][j], ah[i], bh2);
                    mma_bf16(acc[i][j], ah[i], bl2);
                    mma_bf16(acc[i][j], al[i], bh2);
                }
            }
        }

        #pragma unroll
        for (int i = 0; i < 4; i++) {
            int grow0 = qt * 128 + wm + i * 16 + r0;
            #pragma unroll
            for (int j = 0; j < 4; j++) {
                int gcol = kt * 256 + wn + j * 8 + cp;
                float2 v0 = make_float2(acc[i][j][0] * scale, acc[i][j][1] * scale);
                float2 v1 = make_float2(acc[i][j][2] * scale, acc[i][j][3] * scale);
                *(float2*)(g_s + ((size_t)bh * L + grow0) * L + gcol) = v0;
                *(float2*)(g_s + ((size_t)bh * L + grow0 + 8) * L + gcol) = v1;
            }
        }
        __syncthreads();           // all reads of buf done before overwrite
        buf ^= 1;
    }
}

// ---------------------------------------------------------------------------
// Phase 3 (fast path, nv<=1024): entmax-1.5, TWO warps per row (6 heads each).
// ---------------------------------------------------------------------------
__global__ void __launch_bounds__(256) entmax_dense2_kernel(float* __restrict__ out)
{
    __shared__ float sacc[4][1032];

    int tid = threadIdx.x;
    int w = tid >> 5, lane = tid & 31;
    int rowi = w >> 1;
    int half = w & 1;
    int gq = blockIdx.x * 4 + rowi;
    int b = gq / L, qi = gq % L;

    int nv = g_nv[b];
    if (nv > 1024) return;

    float acc[32];
    #pragma unroll
    for (int e = 0; e < 32; e++) acc[e] = 0.f;

    const float invH = 1.0f / 12.0f;

    for (int hh = 0; hh < 6; hh++) {
        int h = half * 6 + hh;
        const float4* row = (const float4*)(g_s + ((size_t)(b * H + h) * L + qi) * L);
        float z[32];
        float m = -1e30f;
        #pragma unroll
        for (int i = 0; i < 8; i++) {
            int e4 = lane + i * 32;
            float4 v = __ldg(row + e4);
            z[i * 4 + 0] = (4 * e4 + 0 < nv) ? v.x : -1e30f;
            z[i * 4 + 1] = (4 * e4 + 1 < nv) ? v.y : -1e30f;
            z[i * 4 + 2] = (4 * e4 + 2 < nv) ? v.z : -1e30f;
            z[i * 4 + 3] = (4 * e4 + 3 < nv) ? v.w : -1e30f;
            m = fmaxf(m, fmaxf(fmaxf(z[i*4], z[i*4+1]), fmaxf(z[i*4+2], z[i*4+3])));
        }
        #pragma unroll
        for (int o = 16; o; o >>= 1) m = fmaxf(m, __shfl_xor_sync(0xffffffffu, m, o));

        float tau = m - 1.0f;
        const float tmax = m - 1e-7f;

        for (int it = 0; it < 20; it++) {
            float s0 = 0.f, s1 = 0.f;
            #pragma unroll
            for (int e = 0; e < 32; e++) {
                float d = fmaxf(z[e] - tau, 0.f);
                s1 += d;
                s0 = fmaf(d, d, s0);
            }
            #pragma unroll
            for (int o = 16; o; o >>= 1) {
                s0 += __shfl_xor_sync(0xffffffffu, s0, o);
                s1 += __shfl_xor_sync(0xffffffffu, s1, o);
            }
            float step;
            if (s0 > 2.0f) step = (s0 - sqrtf(s0)) / s1;
            else           step = (s0 - 1.0f) / (2.0f * s1);
            tau = fminf(tau + step, tmax);
            if (fabsf(step) <= 5e-7f) break;
        }

        #pragma unroll
        for (int e = 0; e < 32; e++) {
            float d = z[e] - tau;
            if (d > 0.f) acc[e] = fmaf(d * d, invH, acc[e]);
        }
    }

    if (half == 1) {
        #pragma unroll
        for (int i = 0; i < 8; i++) {
            int e4 = lane + i * 32;
            *(float4*)&sacc[rowi][4 * e4] = make_float4(acc[i*4], acc[i*4+1], acc[i*4+2], acc[i*4+3]);
        }
    }
    __syncthreads();
    if (half == 0) {
        float* orow = out + ((size_t)b * L + qi) * L;
        #pragma unroll
        for (int i = 0; i < 12; i++)
            ((float4*)orow)[lane + i * 32] = make_float4(0.f, 0.f, 0.f, 0.f);
        __syncwarp();
        #pragma unroll
        for (int i = 0; i < 8; i++) {
            int e4 = lane + i * 32;
            float4 o = *(const float4*)&sacc[rowi][4 * e4];
            float p0 = acc[i*4+0] + o.x;
            float p1 = acc[i*4+1] + o.y;
            float p2 = acc[i*4+2] + o.z;
            float p3 = acc[i*4+3] + o.w;
            if (4 * e4 < nv) {
                ushort4 c4 = *(const ushort4*)&g_cols[b][4 * e4];
                orow[c4.x] = p0;
                if (4 * e4 + 1 < nv) orow[c4.y] = p1;
                if (4 * e4 + 2 < nv) orow[c4.z] = p2;
                if (4 * e4 + 3 < nv) orow[c4.w] = p3;
            }
        }
    }
}

// ---------------------------------------------------------------------------
// Phase 3 (guarded exact fallback, nv>1024): warp per row, C=12.
// ---------------------------------------------------------------------------
__global__ void __launch_bounds__(128) entmax_dense12_kernel(float* __restrict__ out)
{
    int warp = (blockIdx.x * blockDim.x + threadIdx.x) >> 5;
    int lane = threadIdx.x & 31;
    int b = warp / L, qi = warp % L;

    int nv = g_nv[b];
    if (nv <= 1024) return;

    float acc[48];
    #pragma unroll
    for (int e = 0; e < 48; e++) acc[e] = 0.f;

    const float invH = 1.0f / 12.0f;

    for (int h = 0; h < H; h++) {
        const float4* row = (const float4*)(g_s + ((size_t)(b * H + h) * L + qi) * L);
        float z[48];
        float m = -1e30f;
        #pragma unroll
        for (int i = 0; i < 12; i++) {
            int e4 = lane + i * 32;
            float4 v = __ldg(row + e4);
            z[i * 4 + 0] = (4 * e4 + 0 < nv) ? v.x : -1e30f;
            z[i * 4 + 1] = (4 * e4 + 1 < nv) ? v.y : -1e30f;
            z[i * 4 + 2] = (4 * e4 + 2 < nv) ? v.z : -1e30f;
            z[i * 4 + 3] = (4 * e4 + 3 < nv) ? v.w : -1e30f;
            m = fmaxf(m, fmaxf(fmaxf(z[i*4], z[i*4+1]), fmaxf(z[i*4+2], z[i*4+3])));
        }
        #pragma unroll
        for (int o = 16; o; o >>= 1) m = fmaxf(m, __shfl_xor_sync(0xffffffffu, m, o));

        float tau = m - 1.0f;
        const float tmax = m - 1e-7f;

        for (int it = 0; it < 20; it++) {
            float s0 = 0.f, s1 = 0.f;
            #pragma unroll
            for (int e = 0; e < 48; e++) {
                float d = fmaxf(z[e] - tau, 0.f);
                s1 += d;
                s0 = fmaf(d, d, s0);
            }
            #pragma unroll
            for (int o = 16; o; o >>= 1) {
                s0 += __shfl_xor_sync(0xffffffffu, s0, o);
                s1 += __shfl_xor_sync(0xffffffffu, s1, o);
            }
            float step;
            if (s0 > 2.0f) step = (s0 - sqrtf(s0)) / s1;
            else           step = (s0 - 1.0f) / (2.0f * s1);
            tau = fminf(tau + step, tmax);
            if (fabsf(step) <= 5e-7f) break;
        }

        #pragma unroll
        for (int e = 0; e < 48; e++) {
            float d = z[e] - tau;
            if (d > 0.f) acc[e] = fmaf(d * d, invH, acc[e]);
        }
    }

    float* orow = out + ((size_t)b * L + qi) * L;
    #pragma unroll
    for (int i = 0; i < 12; i++)
        ((float4*)orow)[lane + i * 32] = make_float4(0.f, 0.f, 0.f, 0.f);
    __syncwarp();
    #pragma unroll
    for (int i = 0; i < 12; i++) {
        int e4 = lane + i * 32;
        if (4 * e4 < nv) {
            ushort4 c4 = *(const ushort4*)&g_cols[b][4 * e4];
            orow[c4.x] = acc[i * 4 + 0];
            if (4 * e4 + 1 < nv) orow[c4.y] = acc[i * 4 + 1];
            if (4 * e4 + 2 < nv) orow[c4.z] = acc[i * 4 + 2];
            if (4 * e4 + 3 < nv) orow[c4.w] = acc[i * 4 + 3];
        }
    }
}

// ---------------------------------------------------------------------------
extern "C" void kernel_launch(void* const* d_in, const int* in_sizes, int n_in,
                              void* d_out, int out_size)
{
    const float* query = (const float*)d_in[0];
    const float* key   = (const float*)d_in[1];
    const int*   mask  = (const int*)d_in[2];
    const float* wq_w  = (const float*)d_in[3];
    const float* wq_b  = (const float*)d_in[4];
    const float* wk_w  = (const float*)d_in[5];
    const float* wk_b  = (const float*)d_in[6];
    float* out = (float*)d_out;

    (void)in_sizes; (void)n_in; (void)out_size;

    cudaFuncSetAttribute(proj_mma_kernel,
                         cudaFuncAttributeMaxDynamicSharedMemorySize, PROJ_SM_BYTES);
    cudaFuncSetAttribute(scores_mma_kernel,
                         cudaFuncAttributeMaxDynamicSharedMemorySize, SC_SM_BYTES);

    {
        int total4 = (int)(2 * (BLD / 4) + 2 * (DD / 4));
        int nsplit = (total4 + 511) / 512;
        prep_kernel<<<nsplit + B, 512>>>(query, key, wq_w, wk_w, mask, nsplit);     // 0
    }

    dim3 pgrid(D / 256, (B * L) / 128, 2);
    proj_mma_kernel<<<pgrid, 512, PROJ_SM_BYTES>>>(wq_b, wk_b);                     // 1

    dim3 sgrid(L / 128, B * H);
    scores_mma_kernel<<<sgrid, 512, SC_SM_BYTES>>>();                               // 2

    entmax_dense2_kernel<<<(B * L) / 4, 256>>>(out);                                // 3 (captured)
    entmax_dense12_kernel<<<(B * L) / 4, 128>>>(out);                               // 4 fallback
}

// round 16
// speedup vs baseline: 1.0669x; 1.0076x over previous
#include <cuda_runtime.h>
#include <cuda_bf16.h>
#include <cstdint>

#define B 2
#define L 1536
#define D 768
#define H 12
#define DK 64
#define BLD ((size_t)B * L * D)
#define DD  ((size_t)D * D)

// ---------------------------------------------------------------------------
// Scratch (allocation-free rule: static __device__ arrays)
// ---------------------------------------------------------------------------
__device__ __nv_bfloat16 g_xqh[BLD], g_xql[BLD];
__device__ __nv_bfloat16 g_xkh[BLD], g_xkl[BLD];
__device__ __nv_bfloat16 g_wqh[DD],  g_wql[DD];
__device__ __nv_bfloat16 g_wkh[DD],  g_wkl[DD];
__device__ __nv_bfloat16 g_qh[BLD], g_ql[BLD];
__device__ __nv_bfloat16 g_kh[BLD], g_kl[BLD];
__device__ float g_s[(size_t)B * H * L * L];       // z, dense-compacted columns

__device__ int            g_nv[B];
__device__ unsigned short g_cols[B][L];            // dense -> col (zero-init tail)

__device__ __forceinline__ uint32_t smem_u32(const void* p) {
    uint32_t a;
    asm("{ .reg .u64 t; cvta.to.shared.u64 t, %1; cvt.u32.u64 %0, t; }" : "=r"(a) : "l"(p));
    return a;
}
__device__ __forceinline__ void ldsm_x4(uint32_t addr, uint32_t& r0, uint32_t& r1,
                                        uint32_t& r2, uint32_t& r3) {
    asm volatile("ldmatrix.sync.aligned.m8n8.x4.shared.b16 {%0,%1,%2,%3}, [%4];"
                 : "=r"(r0), "=r"(r1), "=r"(r2), "=r"(r3) : "r"(addr));
}
__device__ __forceinline__ void ldsm_x2(uint32_t addr, uint32_t& r0, uint32_t& r1) {
    asm volatile("ldmatrix.sync.aligned.m8n8.x2.shared.b16 {%0,%1}, [%2];"
                 : "=r"(r0), "=r"(r1) : "r"(addr));
}
__device__ __forceinline__ void mma_bf16(float* c, const uint32_t* a, const uint32_t* b) {
    asm volatile(
        "mma.sync.aligned.m16n8k16.row.col.f32.bf16.bf16.f32 "
        "{%0,%1,%2,%3}, {%4,%5,%6,%7}, {%8,%9}, {%0,%1,%2,%3};"
        : "+f"(c[0]), "+f"(c[1]), "+f"(c[2]), "+f"(c[3])
        : "r"(a[0]), "r"(a[1]), "r"(a[2]), "r"(a[3]), "r"(b[0]), "r"(b[1]));
}
__device__ __forceinline__ void cpa16(uint32_t s, const void* g) {
    asm volatile("cp.async.cg.shared.global [%0], [%1], 16;" :: "r"(s), "l"(g));
}
#define CPA_COMMIT() asm volatile("cp.async.commit_group;" ::: "memory")
#define CPA_WAIT1()  asm volatile("cp.async.wait_group 1;" ::: "memory")
#define CPA_WAIT0()  asm volatile("cp.async.wait_group 0;" ::: "memory")

// ---------------------------------------------------------------------------
// Phase 0 (merged): split of all four sources + colmap build, ONE launch.
// Blocks [0, nsplit): split (512 thr, one float4 each).
// Blocks [nsplit, nsplit+B): colmap scan for batch (blockIdx.x - nsplit).
// ---------------------------------------------------------------------------
__global__ void __launch_bounds__(512) prep_kernel(
    const float* __restrict__ query, const float* __restrict__ key,
    const float* __restrict__ wq,    const float* __restrict__ wk,
    const int* __restrict__ mask,    int nsplit)
{
    if ((int)blockIdx.x >= nsplit) {
        // ---- colmap for batch b ----
        int b = blockIdx.x - nsplit;
        int t = threadIdx.x;
        __shared__ int s[512];

        int m0 = mask[b * L + 3 * t + 0] != 0;
        int m1 = mask[b * L + 3 * t + 1] != 0;
        int m2 = mask[b * L + 3 * t + 2] != 0;
        int cnt = m0 + m1 + m2;
        s[t] = cnt;
        __syncthreads();
        for (int off = 1; off < 512; off <<= 1) {
            int v = (t >= off) ? s[t - off] : 0;
            __syncthreads();
            s[t] += v;
            __syncthreads();
        }
        int d = s[t] - cnt;
        if (t == 511) g_nv[b] = s[511];

        int col = 3 * t;
        if (m0) g_cols[b][d++] = (unsigned short)col;
        col++;
        if (m1) g_cols[b][d++] = (unsigned short)col;
        col++;
        if (m2) g_cols[b][d] = (unsigned short)col;
        return;
    }

    // ---- split ----
    const int n4x = (int)(BLD / 4);
    const int n4w = (int)(DD / 4);
    int i = blockIdx.x * 512 + threadIdx.x;

    const float* src;
    __nv_bfloat16 *dh, *dl;
    int li;
    if (i < 2 * n4x) {
        if (i < n4x) { src = query; dh = g_xqh; dl = g_xql; li = i; }
        else         { src = key;   dh = g_xkh; dl = g_xkl; li = i - n4x; }
    } else {
        int j = i - 2 * n4x;
        if (j >= 2 * n4w) return;
        if (j < n4w) { src = wq; dh = g_wqh; dl = g_wql; li = j; }
        else         { src = wk; dh = g_wkh; dl = g_wkl; li = j - n4w; }
    }

    float4 v = ((const float4*)src)[li];
    __nv_bfloat16 h[4], l[4];
    const float* f = &v.x;
    #pragma unroll
    for (int j = 0; j < 4; j++) {
        h[j] = __float2bfloat16(f[j]);
        l[j] = __float2bfloat16(f[j] - __bfloat162float(h[j]));
    }
    ((uint2*)dh)[li] = *(uint2*)h;
    ((uint2*)dl)[li] = *(uint2*)l;
}

// ---------------------------------------------------------------------------
// Phase 1: projection via HMMA bf16x3, cp.async double-buffered K loop.
// ---------------------------------------------------------------------------
#define RP 72
#define P_AH 0
#define P_AL (128 * RP)
#define P_BH (2 * 128 * RP)
#define P_BL (2 * 128 * RP + 256 * RP)
#define PROJ_BUF (2 * 128 * RP + 2 * 256 * RP)
#define PROJ_SM_BYTES (2 * PROJ_BUF * 2)

__global__ void __launch_bounds__(512, 1) proj_mma_kernel(
    const float* __restrict__ biasq, const float* __restrict__ biask)
{
    extern __shared__ __nv_bfloat16 sm[];
    const uint32_t sm_b = smem_u32(sm);

    int nt = blockIdx.x, mt = blockIdx.y, which = blockIdx.z;
    int tid = threadIdx.x;
    int wid = tid >> 5, lane = tid & 31;

    const __nv_bfloat16* xh = which ? g_xkh : g_xqh;
    const __nv_bfloat16* xl = which ? g_xkl : g_xql;
    const __nv_bfloat16* wh = which ? g_wkh : g_wqh;
    const __nv_bfloat16* wl = which ? g_wkl : g_wql;
    __nv_bfloat16* oh = which ? g_kh : g_qh;
    __nv_bfloat16* ol = which ? g_kl : g_ql;
    const float* bias = which ? biask : biasq;

    int wm = (wid & 1) * 64;
    int wn = (wid >> 1) * 32;

    float acc[4][4][4];
    #pragma unroll
    for (int i = 0; i < 4; i++)
        #pragma unroll
        for (int j = 0; j < 4; j++)
            #pragma unroll
            for (int r = 0; r < 4; r++) acc[i][j][r] = 0.f;

    int a_row = lane & 15;
    int a_kh8 = (lane >> 4) * 8;
    int b_row = lane & 7;
    int b_kh8 = ((lane >> 3) & 1) * 8;

    int lrowA[2], lc8A[2], lrowB[4], lc8B[4];
    #pragma unroll
    for (int it = 0; it < 2; it++) { int idx = tid + it * 512; lrowA[it] = idx >> 3; lc8A[it] = (idx & 7) * 8; }
    #pragma unroll
    for (int it = 0; it < 4; it++) { int idx = tid + it * 512; lrowB[it] = idx >> 3; lc8B[it] = (idx & 7) * 8; }

    auto prefetch = [&](int kc, int pb) {
        uint32_t base = sm_b + (uint32_t)pb * PROJ_BUF * 2;
        #pragma unroll
        for (int it = 0; it < 2; it++) {
            size_t g = (size_t)(mt * 128 + lrowA[it]) * D + kc + lc8A[it];
            uint32_t so = (uint32_t)(lrowA[it] * RP + lc8A[it]) * 2;
            cpa16(base + P_AH * 2 + so, xh + g);
            cpa16(base + P_AL * 2 + so, xl + g);
        }
        #pragma unroll
        for (int it = 0; it < 4; it++) {
            size_t g = (size_t)(nt * 256 + lrowB[it]) * D + kc + lc8B[it];
            uint32_t so = (uint32_t)(lrowB[it] * RP + lc8B[it]) * 2;
            cpa16(base + P_BH * 2 + so, wh + g);
            cpa16(base + P_BL * 2 + so, wl + g);
        }
        CPA_COMMIT();
    };

    prefetch(0, 0);

    int buf = 0;
    for (int kci = 0; kci < 12; kci++) {
        if (kci < 11) { prefetch((kci + 1) * 64, buf ^ 1); CPA_WAIT1(); }
        else          { CPA_WAIT0(); }
        __syncthreads();

        uint32_t base = sm_b + (uint32_t)buf * PROJ_BUF * 2;
        uint32_t sAh_b = base + P_AH * 2, sAl_b = base + P_AL * 2;
        uint32_t sBh_b = base + P_BH * 2, sBl_b = base + P_BL * 2;

        #pragma unroll
        for (int ks = 0; ks < 4; ks++) {
            int kb = ks * 16;
            uint32_t ah[4][4], al[4][4];
            #pragma unroll
            for (int i = 0; i < 4; i++) {
                uint32_t off = (uint32_t)((wm + i * 16 + a_row) * RP + kb + a_kh8) * 2;
                ldsm_x4(sAh_b + off, ah[i][0], ah[i][1], ah[i][2], ah[i][3]);
                ldsm_x4(sAl_b + off, al[i][0], al[i][1], al[i][2], al[i][3]);
            }
            #pragma unroll
            for (int j = 0; j < 4; j++) {
                uint32_t off = (uint32_t)((wn + j * 8 + b_row) * RP + kb + b_kh8) * 2;
                uint32_t bh[2], bl[2];
                ldsm_x2(sBh_b + off, bh[0], bh[1]);
                ldsm_x2(sBl_b + off, bl[0], bl[1]);
                #pragma unroll
                for (int i = 0; i < 4; i++) {
                    mma_bf16(acc[i][j], ah[i], bh);
                    mma_bf16(acc[i][j], ah[i], bl);
                    mma_bf16(acc[i][j], al[i], bh);
                }
            }
        }
        __syncthreads();
        buf ^= 1;
    }

    int r0 = lane >> 2;
    int cp = (lane & 3) * 2;
    #pragma unroll
    for (int i = 0; i < 4; i++) {
        int grow0 = mt * 128 + wm + i * 16 + r0;
        #pragma unroll
        for (int j = 0; j < 4; j++) {
            int gcol = nt * 256 + wn + j * 8 + cp;
            float2 bv = *(const float2*)(bias + gcol);
            #pragma unroll
            for (int half = 0; half < 2; half++) {
                float v0 = acc[i][j][half * 2 + 0] + bv.x;
                float v1 = acc[i][j][half * 2 + 1] + bv.y;
                __nv_bfloat16 h0 = __float2bfloat16(v0);
                __nv_bfloat16 h1 = __float2bfloat16(v1);
                __nv_bfloat16 l0 = __float2bfloat16(v0 - __bfloat162float(h0));
                __nv_bfloat16 l1 = __float2bfloat16(v1 - __bfloat162float(h1));
                size_t addr = (size_t)(grow0 + half * 8) * D + gcol;
                __nv_bfloat16 hp[2] = {h0, h1}, lp[2] = {l0, l1};
                *(uint32_t*)(oh + addr) = *(uint32_t*)hp;
                *(uint32_t*)(ol + addr) = *(uint32_t*)lp;
            }
        }
    }
}

// ---------------------------------------------------------------------------
// Phase 2: scores via HMMA bf16x3 — k-loop pipelined version.
// Grid (qt 12, bh 24). Q tile loaded once; gathered K tiles double-buffered
// via cp.async; loop over live k-tiles only (ceil(nv/256)).
// ---------------------------------------------------------------------------
#define SC_Q_H  0
#define SC_Q_L  (128 * RP)
#define SC_QSZ  (2 * 128 * RP)                 // Q elems (hi+lo)
#define SC_KBUF (2 * 256 * RP)                  // per K buffer (hi+lo)
#define SC_K0   SC_QSZ
#define SC_K1   (SC_QSZ + SC_KBUF)
#define SC_SM_BYTES ((SC_QSZ + 2 * SC_KBUF) * 2)   // 184,320 B

__global__ void __launch_bounds__(512, 1) scores_mma_kernel()
{
    extern __shared__ __nv_bfloat16 sm[];
    const uint32_t sm_b = smem_u32(sm);

    int qt = blockIdx.x, bh = blockIdx.y;
    int b = bh / H, h = bh % H;
    int nv = g_nv[b];
    int nkt = (nv + 255) >> 8;                 // live k-tiles

    int tid = threadIdx.x;
    int wid = tid >> 5, lane = tid & 31;

    const __nv_bfloat16* khb = g_kh + (size_t)(b * L) * D + h * DK;
    const __nv_bfloat16* klb = g_kl + (size_t)(b * L) * D + h * DK;

    // ---- load Q tile once (regular loads) ----
    {
        const __nv_bfloat16* qhb = g_qh + (size_t)(b * L + qt * 128) * D + h * DK;
        const __nv_bfloat16* qlb = g_ql + (size_t)(b * L + qt * 128) * D + h * DK;
        #pragma unroll
        for (int it = 0; it < 2; it++) {
            int idx = tid + it * 512;
            int row = idx >> 3;
            int c8  = (idx & 7) * 8;
            *(uint4*)(sm + SC_Q_H + row * RP + c8) = *(const uint4*)(qhb + (size_t)row * D + c8);
            *(uint4*)(sm + SC_Q_L + row * RP + c8) = *(const uint4*)(qlb + (size_t)row * D + c8);
        }
    }

    // ---- gathered K tile prefetch via cp.async ----
    auto prefetch = [&](int kt, int pb) {
        uint32_t kbase = sm_b + (uint32_t)(pb ? SC_K1 : SC_K0) * 2;
        #pragma unroll
        for (int it = 0; it < 4; it++) {
            int idx = tid + it * 512;
            int row = idx >> 3;
            int c8  = (idx & 7) * 8;
            int srow = g_cols[b][kt * 256 + row];         // gathered source row
            uint32_t so = (uint32_t)(row * RP + c8) * 2;
            cpa16(kbase + so,                 khb + (size_t)srow * D + c8);
            cpa16(kbase + SC_KBUF / 2 * 2 + so, klb + (size_t)srow * D + c8); // KL at +256*RP elems
        }
        CPA_COMMIT();
    };
    // NOTE: KL offset within buffer = 256*RP elems = SC_KBUF/2

    if (nkt > 0) prefetch(0, 0);

    int a_row = lane & 15;
    int a_kh8 = (lane >> 4) * 8;
    int b_row = lane & 7;
    int b_kh8 = ((lane >> 3) & 1) * 8;

    int wm = (wid & 1) * 64;
    int wn = (wid >> 1) * 32;

    const float scale = 1.0f / 16.0f;
    int r0 = lane >> 2;
    int cp = (lane & 3) * 2;

    uint32_t sQh_b = sm_b + SC_Q_H * 2;
    uint32_t sQl_b = sm_b + SC_Q_L * 2;

    int buf = 0;
    for (int kt = 0; kt < nkt; kt++) {
        if (kt + 1 < nkt) { prefetch(kt + 1, buf ^ 1); CPA_WAIT1(); }
        else              { CPA_WAIT0(); }
        __syncthreads();

        uint32_t sKh_b = sm_b + (uint32_t)(buf ? SC_K1 : SC_K0) * 2;
        uint32_t sKl_b = sKh_b + (uint32_t)(256 * RP) * 2;

        float acc[4][4][4];
        #pragma unroll
        for (int i = 0; i < 4; i++)
            #pragma unroll
            for (int j = 0; j < 4; j++)
                #pragma unroll
                for (int r = 0; r < 4; r++) acc[i][j][r] = 0.f;

        #pragma unroll
        for (int ks = 0; ks < 4; ks++) {
            int kb = ks * 16;
            uint32_t ah[4][4], al[4][4];
            #pragma unroll
            for (int i = 0; i < 4; i++) {
                uint32_t off = (uint32_t)((wm + i * 16 + a_row) * RP + kb + a_kh8) * 2;
                ldsm_x4(sQh_b + off, ah[i][0], ah[i][1], ah[i][2], ah[i][3]);
                ldsm_x4(sQl_b + off, al[i][0], al[i][1], al[i][2], al[i][3]);
            }
            #pragma unroll
            for (int j = 0; j < 4; j++) {
                uint32_t off = (uint32_t)((wn + j * 8 + b_row) * RP + kb + b_kh8) * 2;
                uint32_t bh2[2], bl2[2];
                ldsm_x2(sKh_b + off, bh2[0], bh2[1]);
                ldsm_x2(sKl_b + off, bl2[0], bl2[1]);
                #pragma unroll
                for (int i = 0; i < 4; i++) {
                    mma_bf16(acc[i][j], ah[i], bh2);
                    mma_bf16(acc[i][j], ah[i], bl2);
                    mma_bf16(acc[i][j], al[i], bh2);
                }
            }
        }

        #pragma unroll
        for (int i = 0; i < 4; i++) {
            int grow0 = qt * 128 + wm + i * 16 + r0;
            #pragma unroll
            for (int j = 0; j < 4; j++) {
                int gcol = kt * 256 + wn + j * 8 + cp;
                float2 v0 = make_float2(acc[i][j][0] * scale, acc[i][j][1] * scale);
                float2 v1 = make_float2(acc[i][j][2] * scale, acc[i][j][3] * scale);
                *(float2*)(g_s + ((size_t)bh * L + grow0) * L + gcol) = v0;
                *(float2*)(g_s + ((size_t)bh * L + grow0 + 8) * L + gcol) = v1;
            }
        }
        __syncthreads();           // all reads of buf done before overwrite
        buf ^= 1;
    }
}

// ---------------------------------------------------------------------------
// Phase 3 (fast path, nv<=1024): entmax-1.5, TWO warps per row (6 heads each).
// ---------------------------------------------------------------------------
__global__ void __launch_bounds__(256) entmax_dense2_kernel(float* __restrict__ out)
{
    __shared__ float sacc[4][1032];

    int tid = threadIdx.x;
    int w = tid >> 5, lane = tid & 31;
    int rowi = w >> 1;
    int half = w & 1;
    int gq = blockIdx.x * 4 + rowi;
    int b = gq / L, qi = gq % L;

    int nv = g_nv[b];
    if (nv > 1024) return;

    float acc[32];
    #pragma unroll
    for (int e = 0; e < 32; e++) acc[e] = 0.f;

    const float invH = 1.0f / 12.0f;

    for (int hh = 0; hh < 6; hh++) {
        int h = half * 6 + hh;
        const float4* row = (const float4*)(g_s + ((size_t)(b * H + h) * L + qi) * L);
        float z[32];
        float m = -1e30f;
        #pragma unroll
        for (int i = 0; i < 8; i++) {
            int e4 = lane + i * 32;
            float4 v = __ldg(row + e4);
            z[i * 4 + 0] = (4 * e4 + 0 < nv) ? v.x : -1e30f;
            z[i * 4 + 1] = (4 * e4 + 1 < nv) ? v.y : -1e30f;
            z[i * 4 + 2] = (4 * e4 + 2 < nv) ? v.z : -1e30f;
            z[i * 4 + 3] = (4 * e4 + 3 < nv) ? v.w : -1e30f;
            m = fmaxf(m, fmaxf(fmaxf(z[i*4], z[i*4+1]), fmaxf(z[i*4+2], z[i*4+3])));
        }
        #pragma unroll
        for (int o = 16; o; o >>= 1) m = fmaxf(m, __shfl_xor_sync(0xffffffffu, m, o));

        float tau = m - 1.0f;
        const float tmax = m - 1e-7f;

        for (int it = 0; it < 20; it++) {
            float s0 = 0.f, s1 = 0.f;
            #pragma unroll
            for (int e = 0; e < 32; e++) {
                float d = fmaxf(z[e] - tau, 0.f);
                s1 += d;
                s0 = fmaf(d, d, s0);
            }
            #pragma unroll
            for (int o = 16; o; o >>= 1) {
                s0 += __shfl_xor_sync(0xffffffffu, s0, o);
                s1 += __shfl_xor_sync(0xffffffffu, s1, o);
            }
            float step;
            if (s0 > 2.0f) step = (s0 - sqrtf(s0)) / s1;
            else           step = (s0 - 1.0f) / (2.0f * s1);
            tau = fminf(tau + step, tmax);
            if (fabsf(step) <= 5e-7f) break;
        }

        #pragma unroll
        for (int e = 0; e < 32; e++) {
            float d = z[e] - tau;
            if (d > 0.f) acc[e] = fmaf(d * d, invH, acc[e]);
        }
    }

    if (half == 1) {
        #pragma unroll
        for (int i = 0; i < 8; i++) {
            int e4 = lane + i * 32;
            *(float4*)&sacc[rowi][4 * e4] = make_float4(acc[i*4], acc[i*4+1], acc[i*4+2], acc[i*4+3]);
        }
    }
    __syncthreads();
    if (half == 0) {
        float* orow = out + ((size_t)b * L + qi) * L;
        #pragma unroll
        for (int i = 0; i < 12; i++)
            ((float4*)orow)[lane + i * 32] = make_float4(0.f, 0.f, 0.f, 0.f);
        __syncwarp();
        #pragma unroll
        for (int i = 0; i < 8; i++) {
            int e4 = lane + i * 32;
            float4 o = *(const float4*)&sacc[rowi][4 * e4];
            float p0 = acc[i*4+0] + o.x;
            float p1 = acc[i*4+1] + o.y;
            float p2 = acc[i*4+2] + o.z;
            float p3 = acc[i*4+3] + o.w;
            if (4 * e4 < nv) {
                ushort4 c4 = *(const ushort4*)&g_cols[b][4 * e4];
                orow[c4.x] = p0;
                if (4 * e4 + 1 < nv) orow[c4.y] = p1;
                if (4 * e4 + 2 < nv) orow[c4.z] = p2;
                if (4 * e4 + 3 < nv) orow[c4.w] = p3;
            }
        }
    }
}

// ---------------------------------------------------------------------------
// Phase 3 (guarded exact fallback, nv>1024): warp per row, C=12.
// ---------------------------------------------------------------------------
__global__ void __launch_bounds__(128) entmax_dense12_kernel(float* __restrict__ out)
{
    int warp = (blockIdx.x * blockDim.x + threadIdx.x) >> 5;
    int lane = threadIdx.x & 31;
    int b = warp / L, qi = warp % L;

    int nv = g_nv[b];
    if (nv <= 1024) return;

    float acc[48];
    #pragma unroll
    for (int e = 0; e < 48; e++) acc[e] = 0.f;

    const float invH = 1.0f / 12.0f;

    for (int h = 0; h < H; h++) {
        const float4* row = (const float4*)(g_s + ((size_t)(b * H + h) * L + qi) * L);
        float z[48];
        float m = -1e30f;
        #pragma unroll
        for (int i = 0; i < 12; i++) {
            int e4 = lane + i * 32;
            float4 v = __ldg(row + e4);
            z[i * 4 + 0] = (4 * e4 + 0 < nv) ? v.x : -1e30f;
            z[i * 4 + 1] = (4 * e4 + 1 < nv) ? v.y : -1e30f;
            z[i * 4 + 2] = (4 * e4 + 2 < nv) ? v.z : -1e30f;
            z[i * 4 + 3] = (4 * e4 + 3 < nv) ? v.w : -1e30f;
            m = fmaxf(m, fmaxf(fmaxf(z[i*4], z[i*4+1]), fmaxf(z[i*4+2], z[i*4+3])));
        }
        #pragma unroll
        for (int o = 16; o; o >>= 1) m = fmaxf(m, __shfl_xor_sync(0xffffffffu, m, o));

        float tau = m - 1.0f;
        const float tmax = m - 1e-7f;

        for (int it = 0; it < 20; it++) {
            float s0 = 0.f, s1 = 0.f;
            #pragma unroll
            for (int e = 0; e < 48; e++) {
                float d = fmaxf(z[e] - tau, 0.f);
                s1 += d;
                s0 = fmaf(d, d, s0);
            }
            #pragma unroll
            for (int o = 16; o; o >>= 1) {
                s0 += __shfl_xor_sync(0xffffffffu, s0, o);
                s1 += __shfl_xor_sync(0xffffffffu, s1, o);
            }
            float step;
            if (s0 > 2.0f) step = (s0 - sqrtf(s0)) / s1;
            else           step = (s0 - 1.0f) / (2.0f * s1);
            tau = fminf(tau + step, tmax);
            if (fabsf(step) <= 5e-7f) break;
        }

        #pragma unroll
        for (int e = 0; e < 48; e++) {
            float d = z[e] - tau;
            if (d > 0.f) acc[e] = fmaf(d * d, invH, acc[e]);
        }
    }

    float* orow = out + ((size_t)b * L + qi) * L;
    #pragma unroll
    for (int i = 0; i < 12; i++)
        ((float4*)orow)[lane + i * 32] = make_float4(0.f, 0.f, 0.f, 0.f);
    __syncwarp();
    #pragma unroll
    for (int i = 0; i < 12; i++) {
        int e4 = lane + i * 32;
        if (4 * e4 < nv) {
            ushort4 c4 = *(const ushort4*)&g_cols[b][4 * e4];
            orow[c4.x] = acc[i * 4 + 0];
            if (4 * e4 + 1 < nv) orow[c4.y] = acc[i * 4 + 1];
            if (4 * e4 + 2 < nv) orow[c4.z] = acc[i * 4 + 2];
            if (4 * e4 + 3 < nv) orow[c4.w] = acc[i * 4 + 3];
        }
    }
}

// ---------------------------------------------------------------------------
extern "C" void kernel_launch(void* const* d_in, const int* in_sizes, int n_in,
                              void* d_out, int out_size)
{
    const float* query = (const float*)d_in[0];
    const float* key   = (const float*)d_in[1];
    const int*   mask  = (const int*)d_in[2];
    const float* wq_w  = (const float*)d_in[3];
    const float* wq_b  = (const float*)d_in[4];
    const float* wk_w  = (const float*)d_in[5];
    const float* wk_b  = (const float*)d_in[6];
    float* out = (float*)d_out;

    (void)in_sizes; (void)n_in; (void)out_size;

    cudaFuncSetAttribute(proj_mma_kernel,
                         cudaFuncAttributeMaxDynamicSharedMemorySize, PROJ_SM_BYTES);
    cudaFuncSetAttribute(scores_mma_kernel,
                         cudaFuncAttributeMaxDynamicSharedMemorySize, SC_SM_BYTES);

    {
        int total4 = (int)(2 * (BLD / 4) + 2 * (DD / 4));
        int nsplit = (total4 + 511) / 512;
        prep_kernel<<<nsplit + B, 512>>>(query, key, wq_w, wk_w, mask, nsplit);     // 0
    }

    dim3 pgrid(D / 256, (B * L) / 128, 2);
    proj_mma_kernel<<<pgrid, 512, PROJ_SM_BYTES>>>(wq_b, wk_b);                     // 1

    dim3 sgrid(L / 128, B * H);
    scores_mma_kernel<<<sgrid, 512, SC_SM_BYTES>>>();                               // 2

    entmax_dense2_kernel<<<(B * L) / 4, 256>>>(out);                                // 3 (captured)
    entmax_dense12_kernel<<<(B * L) / 4, 128>>>(out);                               // 4 fallback
}